// round 5
// baseline (speedup 1.0000x reference)
#include <cuda_runtime.h>
#include <math.h>

#define B_   256
#define T_   512
#define D_   256
#define K_   256

typedef unsigned long long ull;

// Scratch for the precomputed input projection xU [B, T, K] (134 MB, static device mem).
__device__ float g_xu[(size_t)B_ * T_ * K_];

// ---- packed f32x2 helpers (sm_100+): one instr = 2 independent fp32 ops ----
__device__ __forceinline__ ull pk2(float lo, float hi) {
    ull r;
    asm("mov.b64 %0, {%1, %2};"
        : "=l"(r) : "r"(__float_as_uint(lo)), "r"(__float_as_uint(hi)));
    return r;
}
__device__ __forceinline__ void unpk2(ull v, float& lo, float& hi) {
    unsigned int a, b;
    asm("mov.b64 {%0, %1}, %2;" : "=r"(a), "=r"(b) : "l"(v));
    lo = __uint_as_float(a); hi = __uint_as_float(b);
}
// d = a*b + d (packed, exact fp32 fma on each half)
#define FMA2(d, a, b) asm("fma.rn.f32x2 %0, %1, %2, %0;" : "+l"(d) : "l"(a), "l"(b))
#define ADD2(d, a, b) asm("add.rn.f32x2 %0, %1, %2;" : "=l"(d) : "l"(a), "l"(b))

// =====================================================================
// Kernel 1: xU = X @ U + b    (M = B*T = 131072, Kdim = 256, N = 256)
// Tiled SGEMM: 128x128 block tile, 8x8 per-thread tile, BK=8,
// register-prefetch double buffering, packed f32x2 accumulation.
// =====================================================================
#define BM 128
#define BN 128
#define BK 8
#define TM 8
#define TN 8

__global__ __launch_bounds__(256) void xu_gemm_kernel(
    const float* __restrict__ X,     // [B*T, D]
    const float* __restrict__ U,     // [D, K]
    const float* __restrict__ bias)  // [K]
{
    __shared__ float As[BK][BM + 4];   // transposed A tile (row stride 132 = 16B-aligned)
    __shared__ float Bs[BK][BN];

    const int m0 = blockIdx.x * BM;
    const int n0 = blockIdx.y * BN;
    const int tid = (int)threadIdx.x;
    const int tx = tid & 15;          // 0..15  (N direction)
    const int ty = tid >> 4;          // 0..15  (M direction)

    // acc2[i][p] packs columns (2p, 2p+1) of row i
    ull acc2[TM][TN / 2];
#pragma unroll
    for (int i = 0; i < TM; i++)
#pragma unroll
        for (int p = 0; p < TN / 2; p++) acc2[i][p] = 0ull;

    const int a_row = tid >> 1;           // 0..127
    const int a_col = (tid & 1) * 4;      // 0 or 4
    const int b_row = tid >> 5;           // 0..7
    const int b_col = (tid & 31) * 4;     // 0..124

    // Prefetch first tile into registers
    float4 av = *(const float4*)&X[(size_t)(m0 + a_row) * D_ + a_col];
    float4 bv = *(const float4*)&U[(size_t)b_row * K_ + (n0 + b_col)];

    for (int k0 = 0; k0 < D_; k0 += BK) {
        As[a_col + 0][a_row] = av.x;
        As[a_col + 1][a_row] = av.y;
        As[a_col + 2][a_row] = av.z;
        As[a_col + 3][a_row] = av.w;
        *(float4*)&Bs[b_row][b_col] = bv;
        __syncthreads();

        if (k0 + BK < D_) {
            av = *(const float4*)&X[(size_t)(m0 + a_row) * D_ + (k0 + BK + a_col)];
            bv = *(const float4*)&U[(size_t)(k0 + BK + b_row) * K_ + (n0 + b_col)];
        }

#pragma unroll
        for (int kk = 0; kk < BK; kk++) {
            const float4 a0 = *(const float4*)&As[kk][ty * TM + 0];
            const float4 a1 = *(const float4*)&As[kk][ty * TM + 4];
            // b pairs are natural: Bs row is 16B-aligned, tx*TN is 32B-aligned
            const ulonglong2 b01 = *(const ulonglong2*)&Bs[kk][tx * TN + 0];
            const ulonglong2 b23 = *(const ulonglong2*)&Bs[kk][tx * TN + 4];

            ull ap[TM];
            ap[0] = pk2(a0.x, a0.x); ap[1] = pk2(a0.y, a0.y);
            ap[2] = pk2(a0.z, a0.z); ap[3] = pk2(a0.w, a0.w);
            ap[4] = pk2(a1.x, a1.x); ap[5] = pk2(a1.y, a1.y);
            ap[6] = pk2(a1.z, a1.z); ap[7] = pk2(a1.w, a1.w);

#pragma unroll
            for (int i = 0; i < TM; i++) {
                FMA2(acc2[i][0], ap[i], b01.x);
                FMA2(acc2[i][1], ap[i], b01.y);
                FMA2(acc2[i][2], ap[i], b23.x);
                FMA2(acc2[i][3], ap[i], b23.y);
            }
        }
        __syncthreads();
    }

    // Epilogue: add bias (packed), store to g_xu
    ull bp[TN / 2];
#pragma unroll
    for (int p = 0; p < TN / 2; p++)
        bp[p] = pk2(bias[n0 + tx * TN + 2 * p], bias[n0 + tx * TN + 2 * p + 1]);

#pragma unroll
    for (int i = 0; i < TM; i++) {
        const size_t m = (size_t)(m0 + ty * TM + i);
        ull v0, v1, v2, v3;
        ADD2(v0, acc2[i][0], bp[0]);
        ADD2(v1, acc2[i][1], bp[1]);
        ADD2(v2, acc2[i][2], bp[2]);
        ADD2(v3, acc2[i][3], bp[3]);
        ulonglong2 s0; s0.x = v0; s0.y = v1;
        ulonglong2 s1; s1.x = v2; s1.y = v3;
        *(ulonglong2*)&g_xu[m * K_ + (n0 + tx * TN + 0)] = s0;
        *(ulonglong2*)&g_xu[m * K_ + (n0 + tx * TN + 4)] = s1;
    }
}

// =====================================================================
// Kernel 2: persistent per-batch recurrence, 512 threads/block, f32x2.
//   h_t[b,:] = tanh(xu[b,t,:] + h_{t-1}[b,:] @ W)
// 128 blocks; block owns batches {2bx, 2bx+1}.
// W rows 0..127 in smem; rows 128..255 in registers (32 ull/thread).
// h stored in smem PRE-DUPLICATED: hs[j] = (h[j], h[j]) as one ull, so
// packed broadcast multipliers come straight from LDS (no mov.b64 packs
// in the inner loop). Thread (g, c): g = tid>>6 (j-group 16 rows),
// c = tid&63 (columns 4c..4c+3, i.e. 2 packed accumulator lanes).
// Partials (8 groups x 2 batches x 256 cols) reduced through smem.
// =====================================================================
#define RNN_SMEM_FLOATS (128 * 256 + 1024 + 16 * 256)
#define RNN_SMEM_BYTES  (RNN_SMEM_FLOATS * 4)

__global__ __launch_bounds__(512, 1) void rnn_recurrence_kernel(
    const float* __restrict__ W,    // [K, K] row-major: W[j*K + k]
    float* __restrict__ out)        // [B, K]
{
    extern __shared__ float sm[];
    float* Wsm = sm;                          // 128*256 floats (131072 B)
    ull*   hs0 = (ull*)(sm + 128 * 256);      // 256 ull: (h,h) dup, batch b0
    ull*   hs1 = hs0 + 256;                   // 256 ull: batch b1
    float* part = sm + 128 * 256 + 1024;      // 16*256 floats

    const int tid = (int)threadIdx.x;
    const int g   = tid >> 6;        // 0..7
    const int c   = tid & 63;        // 0..63
    const int col = c * 4;           // base column (k), 16B-aligned
    const int b0  = blockIdx.x * 2;

    // --- Load W rows 0..127 into smem ---
    for (int i = tid; i < 128 * 64; i += 512) {
        const int row = i >> 6;
        const int c4  = (i & 63) * 4;
        *(float4*)&Wsm[row * 256 + c4] = *(const float4*)&W[row * 256 + c4];
    }
    // --- W rows [128+16g, 128+16g+16) cols [col, col+4) into packed registers ---
    ull wlo[16], whi[16];
#pragma unroll
    for (int jj = 0; jj < 16; jj++) {
        const ulonglong2 wv = *(const ulonglong2*)&W[(128 + g * 16 + jj) * 256 + col];
        wlo[jj] = wv.x; whi[jj] = wv.y;
    }
    // --- h0 = 0 (duplicated zeros) ---
    if (tid < 256) { hs0[tid] = 0ull; hs1[tid] = 0ull; }
    __syncthreads();

    // Reduce-phase ownership: thread -> (batch rb, column rk)
    const int rb = tid >> 8;         // 0 or 1
    const int rk = tid & 255;        // 0..255
    const float* xup = g_xu + ((size_t)(b0 + rb) * T_) * K_ + rk;

    const int js = g * 16;
    float hn = 0.0f;

    for (int ts = 0; ts < T_; ts++) {
        const float xv = xup[(size_t)ts * K_];   // consumed after barrier 1

        ull a0lo = 0ull, a0hi = 0ull, a1lo = 0ull, a1hi = 0ull;

        // smem W rows [16g, 16g+16); h dup-pairs loaded 2 rows at a time
#pragma unroll
        for (int jj = 0; jj < 16; jj += 2) {
            const int j = js + jj;
            const ulonglong2 h0 = *(const ulonglong2*)&hs0[j]; // (dup j, dup j+1)
            const ulonglong2 h1 = *(const ulonglong2*)&hs1[j];
            const ulonglong2 wa = *(const ulonglong2*)&Wsm[(j + 0) * 256 + col];
            const ulonglong2 wb = *(const ulonglong2*)&Wsm[(j + 1) * 256 + col];
            FMA2(a0lo, wa.x, h0.x); FMA2(a0hi, wa.y, h0.x);
            FMA2(a1lo, wa.x, h1.x); FMA2(a1hi, wa.y, h1.x);
            FMA2(a0lo, wb.x, h0.y); FMA2(a0hi, wb.y, h0.y);
            FMA2(a1lo, wb.x, h1.y); FMA2(a1hi, wb.y, h1.y);
        }
        // register W rows [128+16g, 128+16g+16)
#pragma unroll
        for (int jj = 0; jj < 16; jj += 2) {
            const int j = 128 + js + jj;
            const ulonglong2 h0 = *(const ulonglong2*)&hs0[j];
            const ulonglong2 h1 = *(const ulonglong2*)&hs1[j];
            FMA2(a0lo, wlo[jj], h0.x); FMA2(a0hi, whi[jj], h0.x);
            FMA2(a1lo, wlo[jj], h1.x); FMA2(a1hi, whi[jj], h1.x);
            FMA2(a0lo, wlo[jj + 1], h0.y); FMA2(a0hi, whi[jj + 1], h0.y);
            FMA2(a1lo, wlo[jj + 1], h1.y); FMA2(a1hi, whi[jj + 1], h1.y);
        }

        // write partials: part[(g*2 + b)*256 + col] (bit-identical to float4)
        ulonglong2 s0; s0.x = a0lo; s0.y = a0hi;
        ulonglong2 s1; s1.x = a1lo; s1.y = a1hi;
        *(ulonglong2*)&part[(g * 2 + 0) * 256 + col] = s0;
        *(ulonglong2*)&part[(g * 2 + 1) * 256 + col] = s1;
        __syncthreads();

        // reduce 8 group-partials; thread owns (rb, rk)
        float s = 0.0f;
#pragma unroll
        for (int gg = 0; gg < 8; gg++) s += part[(gg * 2 + rb) * 256 + rk];

        hn = tanhf(xv + s);
        const ull hp = pk2(hn, hn);
        if (rb == 0) hs0[rk] = hp; else hs1[rk] = hp;
        __syncthreads();
    }

    // final hidden state -> out [B, K]
    out[(size_t)(b0 + rb) * K_ + rk] = hn;
}

// =====================================================================
// Harness entry
// metadata order: inputs [B,T,D] f32, U [D,K] f32, W [K,K] f32, b [K] f32
// output: [B,1,K] f32
// =====================================================================
extern "C" void kernel_launch(void* const* d_in, const int* in_sizes, int n_in,
                              void* d_out, int out_size) {
    const float* X    = (const float*)d_in[0];
    const float* U    = (const float*)d_in[1];
    const float* W    = (const float*)d_in[2];
    const float* bias = (const float*)d_in[3];
    float* out = (float*)d_out;

    cudaError_t attr_rc = cudaFuncSetAttribute(
        rnn_recurrence_kernel,
        cudaFuncAttributeMaxDynamicSharedMemorySize,
        RNN_SMEM_BYTES);
    (void)attr_rc;

    dim3 gemm_grid(B_ * T_ / BM, K_ / BN);   // (1024, 2)
    xu_gemm_kernel<<<gemm_grid, 256>>>(X, U, bias);

    rnn_recurrence_kernel<<<128, 512, RNN_SMEM_BYTES>>>(W, out);
}

// round 8
// speedup vs baseline: 1.1111x; 1.1111x over previous
#include <cuda_runtime.h>
#include <cuda_bf16.h>
#include <math.h>

#define B_   256
#define T_   512
#define D_   256
#define K_   256

// Scratch: precomputed input projection xU [B, T, K] (134 MB).
__device__ float g_xu[(size_t)B_ * T_ * K_];
// U split into 3 bf16 planes (hi, mid, lo): 24 mantissa bits total.
__device__ __nv_bfloat16 g_Uhi[D_ * K_];
__device__ __nv_bfloat16 g_Umid[D_ * K_];
__device__ __nv_bfloat16 g_Ulo[D_ * K_];

// =====================================================================
// Kernel 0: split U into 3 bf16 planes.
// =====================================================================
__global__ void u_split_kernel(const float* __restrict__ U) {
    const int i = blockIdx.x * 256 + threadIdx.x;
    const float x = U[i];
    const __nv_bfloat16 hi = __float2bfloat16(x);
    const float r1 = x - __bfloat162float(hi);
    const __nv_bfloat16 mid = __float2bfloat16(r1);
    const float r2 = r1 - __bfloat162float(mid);
    g_Uhi[i]  = hi;
    g_Umid[i] = mid;
    g_Ulo[i]  = __float2bfloat16(r2);
}

// =====================================================================
// Kernel 1: xU = X @ U + b via bf16 mma.sync with 3-plane split.
//   Block tile 128(M) x 128(N), BK=16, 256 threads = 8 warps.
//   Warp grid 4(M) x 2(N): warp tile 32 x 64.
//   Per (m16,n8) micro tile: 6 mma terms: hh, h*mid, mid*h, h*lo, lo*h, mid*mid.
//   X is split to bf16 planes on the fly while staging to smem.
// =====================================================================
#define GBK 16
// sA: [plane][row 128][k 24pad] bf16 ; sB: [plane][k 16][n 136pad] bf16
#define SA_STRIDE 24
#define SB_STRIDE 136

__device__ __forceinline__ unsigned smem_u32(const void* p) {
    return (unsigned)__cvta_generic_to_shared(p);
}

__device__ __forceinline__ void ldm_x4(unsigned& r0, unsigned& r1, unsigned& r2, unsigned& r3, unsigned addr) {
    asm volatile("ldmatrix.sync.aligned.m8n8.x4.shared.b16 {%0,%1,%2,%3}, [%4];"
                 : "=r"(r0), "=r"(r1), "=r"(r2), "=r"(r3) : "r"(addr));
}
__device__ __forceinline__ void ldm_x2_trans(unsigned& r0, unsigned& r1, unsigned addr) {
    asm volatile("ldmatrix.sync.aligned.m8n8.x2.trans.shared.b16 {%0,%1}, [%2];"
                 : "=r"(r0), "=r"(r1) : "r"(addr));
}
__device__ __forceinline__ void mma_bf16(float* c, const unsigned* a, const unsigned* b) {
    asm volatile(
        "mma.sync.aligned.m16n8k16.row.col.f32.bf16.bf16.f32 "
        "{%0,%1,%2,%3}, {%4,%5,%6,%7}, {%8,%9}, {%0,%1,%2,%3};"
        : "+f"(c[0]), "+f"(c[1]), "+f"(c[2]), "+f"(c[3])
        : "r"(a[0]), "r"(a[1]), "r"(a[2]), "r"(a[3]), "r"(b[0]), "r"(b[1]));
}

__global__ __launch_bounds__(256) void xu_gemm_mma_kernel(
    const float* __restrict__ X,     // [B*T, D]
    const float* __restrict__ bias)  // [K]
{
    __shared__ __nv_bfloat16 sA[3][128][SA_STRIDE];
    __shared__ __nv_bfloat16 sB[3][GBK][SB_STRIDE];

    const int m0 = blockIdx.x * 128;
    const int n0 = blockIdx.y * 128;
    const int tid = (int)threadIdx.x;
    const int lane = tid & 31;
    const int wid = tid >> 5;
    const int wm = (wid >> 1) * 32;     // warp M offset 0/32/64/96
    const int wn = (wid & 1) * 64;      // warp N offset 0/64

    // X stage mapping: row = tid>>1 (0..127), colgroup = (tid&1)*8
    const int xa_row = tid >> 1;
    const int xa_cg  = (tid & 1) * 8;
    // U stage mapping: krow = tid>>4 (0..15), ncol8 = (tid&15)*8
    const int ub_k   = tid >> 4;
    const int ub_n   = (tid & 15) * 8;

    float c[2][8][4];
#pragma unroll
    for (int mt = 0; mt < 2; mt++)
#pragma unroll
        for (int nt = 0; nt < 8; nt++)
#pragma unroll
            for (int q = 0; q < 4; q++) c[mt][nt][q] = 0.0f;

    // ldmatrix lane addressing (precompute row/col pieces)
    const int lq  = lane >> 3;       // quadrant id 0..3
    const int lr  = lane & 7;        // row within quadrant
    const int a_r = (lq & 1) * 8 + lr;      // + mt*16 + wm
    const int a_k = (lq >> 1) * 8;
    const int bl  = lane & 15;
    const int b_k = (bl >> 3) * 8 + (bl & 7);

    for (int k0 = 0; k0 < D_; k0 += GBK) {
        // ---- stage X tile (fp32 -> 3 bf16 planes) ----
        const float4 xv0 = *(const float4*)&X[(size_t)(m0 + xa_row) * D_ + (k0 + xa_cg)];
        const float4 xv1 = *(const float4*)&X[(size_t)(m0 + xa_row) * D_ + (k0 + xa_cg + 4)];
        float xs[8] = {xv0.x, xv0.y, xv0.z, xv0.w, xv1.x, xv1.y, xv1.z, xv1.w};
#pragma unroll
        for (int i = 0; i < 8; i += 2) {
            __nv_bfloat162 h2, m2, l2;
            {
                const float x = xs[i];
                const __nv_bfloat16 hi = __float2bfloat16(x);
                const float r1 = x - __bfloat162float(hi);
                const __nv_bfloat16 mid = __float2bfloat16(r1);
                const float r2 = r1 - __bfloat162float(mid);
                h2.x = hi; m2.x = mid; l2.x = __float2bfloat16(r2);
            }
            {
                const float x = xs[i + 1];
                const __nv_bfloat16 hi = __float2bfloat16(x);
                const float r1 = x - __bfloat162float(hi);
                const __nv_bfloat16 mid = __float2bfloat16(r1);
                const float r2 = r1 - __bfloat162float(mid);
                h2.y = hi; m2.y = mid; l2.y = __float2bfloat16(r2);
            }
            *(__nv_bfloat162*)&sA[0][xa_row][xa_cg + i] = h2;
            *(__nv_bfloat162*)&sA[1][xa_row][xa_cg + i] = m2;
            *(__nv_bfloat162*)&sA[2][xa_row][xa_cg + i] = l2;
        }
        // ---- stage U planes (bf16, 16B vector copies) ----
        {
            const size_t uoff = (size_t)(k0 + ub_k) * K_ + (n0 + ub_n);
            *(uint4*)&sB[0][ub_k][ub_n] = *(const uint4*)&g_Uhi[uoff];
            *(uint4*)&sB[1][ub_k][ub_n] = *(const uint4*)&g_Umid[uoff];
            *(uint4*)&sB[2][ub_k][ub_n] = *(const uint4*)&g_Ulo[uoff];
        }
        __syncthreads();

        // ---- A fragments: [mt][plane][4] ----
        unsigned afr[2][3][4];
#pragma unroll
        for (int mt = 0; mt < 2; mt++) {
            const int row = wm + mt * 16 + a_r;
#pragma unroll
            for (int p = 0; p < 3; p++) {
                const unsigned addr = smem_u32(&sA[p][row][a_k]);
                ldm_x4(afr[mt][p][0], afr[mt][p][1], afr[mt][p][2], afr[mt][p][3], addr);
            }
        }

        // ---- loop over n8 tiles; B fragments transient ----
#pragma unroll
        for (int nt = 0; nt < 8; nt++) {
            unsigned bfr[3][2];
#pragma unroll
            for (int p = 0; p < 3; p++) {
                const unsigned addr = smem_u32(&sB[p][b_k][wn + nt * 8]);
                ldm_x2_trans(bfr[p][0], bfr[p][1], addr);
            }
#pragma unroll
            for (int mt = 0; mt < 2; mt++) {
                mma_bf16(c[mt][nt], afr[mt][0], bfr[0]);   // hi*hi
                mma_bf16(c[mt][nt], afr[mt][0], bfr[1]);   // hi*mid
                mma_bf16(c[mt][nt], afr[mt][1], bfr[0]);   // mid*hi
                mma_bf16(c[mt][nt], afr[mt][0], bfr[2]);   // hi*lo
                mma_bf16(c[mt][nt], afr[mt][2], bfr[0]);   // lo*hi
                mma_bf16(c[mt][nt], afr[mt][1], bfr[1]);   // mid*mid
            }
        }
        __syncthreads();
    }

    // ---- epilogue: add bias, store fp32 ----
    const int gid = lane >> 2;
    const int tig = lane & 3;
#pragma unroll
    for (int nt = 0; nt < 8; nt++) {
        const int col = n0 + wn + nt * 8 + 2 * tig;
        const float2 bv = *(const float2*)&bias[col];
#pragma unroll
        for (int mt = 0; mt < 2; mt++) {
            const size_t r0 = (size_t)(m0 + wm + mt * 16 + gid);
            float2 v0; v0.x = c[mt][nt][0] + bv.x; v0.y = c[mt][nt][1] + bv.y;
            float2 v1; v1.x = c[mt][nt][2] + bv.x; v1.y = c[mt][nt][3] + bv.y;
            *(float2*)&g_xu[r0 * K_ + col]       = v0;
            *(float2*)&g_xu[(r0 + 8) * K_ + col] = v1;
        }
    }
}

// =====================================================================
// Kernel 2: persistent per-batch recurrence, 512 threads/block (scalar,
// best-known R4 configuration: 741us).
// =====================================================================
#define RNN_SMEM_FLOATS (128 * 256 + 2 * 256 + 16 * 256)
#define RNN_SMEM_BYTES  (RNN_SMEM_FLOATS * 4)

__global__ __launch_bounds__(512, 1) void rnn_recurrence_kernel(
    const float* __restrict__ W,    // [K, K] row-major: W[j*K + k]
    float* __restrict__ out)        // [B, K]
{
    extern __shared__ float sm[];
    float* Wsm  = sm;                  // 128*256 floats
    float* hs0  = sm + 128 * 256;      // 256 floats: h for batch b0
    float* hs1  = hs0 + 256;           // 256 floats: h for batch b1
    float* part = hs1 + 256;           // 16*256 floats: part[(g*2+b)*256 + k]

    const int tid = (int)threadIdx.x;
    const int g   = tid >> 6;        // 0..7
    const int c   = tid & 63;        // 0..63
    const int col = c * 4;           // base column (k)
    const int b0  = blockIdx.x * 2;

    for (int i = tid; i < 128 * 64; i += 512) {
        const int row = i >> 6;
        const int c4  = (i & 63) * 4;
        *(float4*)&Wsm[row * 256 + c4] = *(const float4*)&W[row * 256 + c4];
    }
    float4 wreg[16];
#pragma unroll
    for (int jj = 0; jj < 16; jj++) {
        wreg[jj] = *(const float4*)&W[(128 + g * 16 + jj) * 256 + col];
    }
    if (tid < 256) { hs0[tid] = 0.0f; hs1[tid] = 0.0f; }
    __syncthreads();

    const int rb = tid >> 8;         // 0 or 1
    const int rk = tid & 255;        // 0..255
    const float* xup = g_xu + ((size_t)(b0 + rb) * T_) * K_ + rk;

    const int js = g * 16;
    float hn = 0.0f;

    for (int ts = 0; ts < T_; ts++) {
        const float xv = xup[(size_t)ts * K_];

        float4 acc0 = make_float4(0.f, 0.f, 0.f, 0.f);
        float4 acc1 = make_float4(0.f, 0.f, 0.f, 0.f);

#pragma unroll
        for (int jj = 0; jj < 16; jj += 4) {
            const float4 h0 = *(const float4*)&hs0[js + jj];
            const float4 h1 = *(const float4*)&hs1[js + jj];
            {
                const float4 w = *(const float4*)&Wsm[(js + jj + 0) * 256 + col];
                acc0.x = fmaf(w.x, h0.x, acc0.x); acc0.y = fmaf(w.y, h0.x, acc0.y);
                acc0.z = fmaf(w.z, h0.x, acc0.z); acc0.w = fmaf(w.w, h0.x, acc0.w);
                acc1.x = fmaf(w.x, h1.x, acc1.x); acc1.y = fmaf(w.y, h1.x, acc1.y);
                acc1.z = fmaf(w.z, h1.x, acc1.z); acc1.w = fmaf(w.w, h1.x, acc1.w);
            }
            {
                const float4 w = *(const float4*)&Wsm[(js + jj + 1) * 256 + col];
                acc0.x = fmaf(w.x, h0.y, acc0.x); acc0.y = fmaf(w.y, h0.y, acc0.y);
                acc0.z = fmaf(w.z, h0.y, acc0.z); acc0.w = fmaf(w.w, h0.y, acc0.w);
                acc1.x = fmaf(w.x, h1.y, acc1.x); acc1.y = fmaf(w.y, h1.y, acc1.y);
                acc1.z = fmaf(w.z, h1.y, acc1.z); acc1.w = fmaf(w.w, h1.y, acc1.w);
            }
            {
                const float4 w = *(const float4*)&Wsm[(js + jj + 2) * 256 + col];
                acc0.x = fmaf(w.x, h0.z, acc0.x); acc0.y = fmaf(w.y, h0.z, acc0.y);
                acc0.z = fmaf(w.z, h0.z, acc0.z); acc0.w = fmaf(w.w, h0.z, acc0.w);
                acc1.x = fmaf(w.x, h1.z, acc1.x); acc1.y = fmaf(w.y, h1.z, acc1.y);
                acc1.z = fmaf(w.z, h1.z, acc1.z); acc1.w = fmaf(w.w, h1.z, acc1.w);
            }
            {
                const float4 w = *(const float4*)&Wsm[(js + jj + 3) * 256 + col];
                acc0.x = fmaf(w.x, h0.w, acc0.x); acc0.y = fmaf(w.y, h0.w, acc0.y);
                acc0.z = fmaf(w.z, h0.w, acc0.z); acc0.w = fmaf(w.w, h0.w, acc0.w);
                acc1.x = fmaf(w.x, h1.w, acc1.x); acc1.y = fmaf(w.y, h1.w, acc1.y);
                acc1.z = fmaf(w.z, h1.w, acc1.z); acc1.w = fmaf(w.w, h1.w, acc1.w);
            }
        }
#pragma unroll
        for (int jj = 0; jj < 16; jj += 4) {
            const float4 h0 = *(const float4*)&hs0[128 + js + jj];
            const float4 h1 = *(const float4*)&hs1[128 + js + jj];
            {
                const float4 w = wreg[jj + 0];
                acc0.x = fmaf(w.x, h0.x, acc0.x); acc0.y = fmaf(w.y, h0.x, acc0.y);
                acc0.z = fmaf(w.z, h0.x, acc0.z); acc0.w = fmaf(w.w, h0.x, acc0.w);
                acc1.x = fmaf(w.x, h1.x, acc1.x); acc1.y = fmaf(w.y, h1.x, acc1.y);
                acc1.z = fmaf(w.z, h1.x, acc1.z); acc1.w = fmaf(w.w, h1.x, acc1.w);
            }
            {
                const float4 w = wreg[jj + 1];
                acc0.x = fmaf(w.x, h0.y, acc0.x); acc0.y = fmaf(w.y, h0.y, acc0.y);
                acc0.z = fmaf(w.z, h0.y, acc0.z); acc0.w = fmaf(w.w, h0.y, acc0.w);
                acc1.x = fmaf(w.x, h1.y, acc1.x); acc1.y = fmaf(w.y, h1.y, acc1.y);
                acc1.z = fmaf(w.z, h1.y, acc1.z); acc1.w = fmaf(w.w, h1.y, acc1.w);
            }
            {
                const float4 w = wreg[jj + 2];
                acc0.x = fmaf(w.x, h0.z, acc0.x); acc0.y = fmaf(w.y, h0.z, acc0.y);
                acc0.z = fmaf(w.z, h0.z, acc0.z); acc0.w = fmaf(w.w, h0.z, acc0.w);
                acc1.x = fmaf(w.x, h1.z, acc1.x); acc1.y = fmaf(w.y, h1.z, acc1.y);
                acc1.z = fmaf(w.z, h1.z, acc1.z); acc1.w = fmaf(w.w, h1.z, acc1.w);
            }
            {
                const float4 w = wreg[jj + 3];
                acc0.x = fmaf(w.x, h0.w, acc0.x); acc0.y = fmaf(w.y, h0.w, acc0.y);
                acc0.z = fmaf(w.z, h0.w, acc0.z); acc0.w = fmaf(w.w, h0.w, acc0.w);
                acc1.x = fmaf(w.x, h1.w, acc1.x); acc1.y = fmaf(w.y, h1.w, acc1.y);
                acc1.z = fmaf(w.z, h1.w, acc1.z); acc1.w = fmaf(w.w, h1.w, acc1.w);
            }
        }

        *(float4*)&part[(g * 2 + 0) * 256 + col] = acc0;
        *(float4*)&part[(g * 2 + 1) * 256 + col] = acc1;
        __syncthreads();

        float s = 0.0f;
#pragma unroll
        for (int gg = 0; gg < 8; gg++) s += part[(gg * 2 + rb) * 256 + rk];

        hn = tanhf(xv + s);
        if (rb == 0) hs0[rk] = hn; else hs1[rk] = hn;
        __syncthreads();
    }

    out[(size_t)(b0 + rb) * K_ + rk] = hn;
}

// =====================================================================
// Harness entry
// metadata order: inputs [B,T,D] f32, U [D,K] f32, W [K,K] f32, b [K] f32
// output: [B,1,K] f32
// =====================================================================
extern "C" void kernel_launch(void* const* d_in, const int* in_sizes, int n_in,
                              void* d_out, int out_size) {
    const float* X    = (const float*)d_in[0];
    const float* U    = (const float*)d_in[1];
    const float* W    = (const float*)d_in[2];
    const float* bias = (const float*)d_in[3];
    float* out = (float*)d_out;

    cudaError_t attr_rc = cudaFuncSetAttribute(
        rnn_recurrence_kernel,
        cudaFuncAttributeMaxDynamicSharedMemorySize,
        RNN_SMEM_BYTES);
    (void)attr_rc;

    u_split_kernel<<<D_ * K_ / 256, 256>>>(U);

    dim3 gemm_grid(B_ * T_ / 128, K_ / 128);   // (1024, 2)
    xu_gemm_mma_kernel<<<gemm_grid, 256>>>(X, bias);

    rnn_recurrence_kernel<<<128, 512, RNN_SMEM_BYTES>>>(W, out);
}

// round 11
// speedup vs baseline: 1.2897x; 1.1608x over previous
#include <cuda_runtime.h>
#include <cuda_bf16.h>
#include <math.h>

#define B_   256
#define T_   512
#define D_   256
#define K_   256

// Scratch: precomputed input projection xU [B, T, K] (134 MB).
__device__ float g_xu[(size_t)B_ * T_ * K_];
// U split into 2 bf16 planes (hi, mid): 16 mantissa bits total.
__device__ __nv_bfloat16 g_Uhi[D_ * K_];
__device__ __nv_bfloat16 g_Umid[D_ * K_];

// =====================================================================
// Kernel 0: split U into 2 bf16 planes.
// =====================================================================
__global__ void u_split_kernel(const float* __restrict__ U) {
    const int i = blockIdx.x * 256 + threadIdx.x;
    const float x = U[i];
    const __nv_bfloat16 hi = __float2bfloat16(x);
    const float r1 = x - __bfloat162float(hi);
    g_Uhi[i]  = hi;
    g_Umid[i] = __float2bfloat16(r1);
}

// =====================================================================
// Kernel 1: xU = X @ U + b via bf16 mma.sync, 2-plane split, 3 terms:
//   x*u ~= xh*uh + xh*um + xm*uh      (drops ~2^-16-relative terms)
// Block tile 128(M) x 128(N), BK=16, 256 threads = 8 warps (4Mx2N).
// Double-buffered smem; U planes staged via cp.async; X staged via
// LDG->split->STS overlapped with the current stage's mma work.
// =====================================================================
#define GBK 16
#define SA_STRIDE 24    // bf16 elems per row (48B, 16B-aligned)
#define SB_STRIDE 136   // bf16 elems per row (272B, 16B-aligned)

__device__ __forceinline__ unsigned smem_u32(const void* p) {
    return (unsigned)__cvta_generic_to_shared(p);
}
__device__ __forceinline__ void cp_async16(void* dst, const void* src) {
    asm volatile("cp.async.ca.shared.global [%0], [%1], 16;"
                 :: "r"(smem_u32(dst)), "l"(src));
}
__device__ __forceinline__ void cp_commit() {
    asm volatile("cp.async.commit_group;");
}
__device__ __forceinline__ void cp_wait_all() {
    asm volatile("cp.async.wait_group 0;");
}

__device__ __forceinline__ void ldm_x4(unsigned& r0, unsigned& r1, unsigned& r2, unsigned& r3, unsigned addr) {
    asm volatile("ldmatrix.sync.aligned.m8n8.x4.shared.b16 {%0,%1,%2,%3}, [%4];"
                 : "=r"(r0), "=r"(r1), "=r"(r2), "=r"(r3) : "r"(addr));
}
__device__ __forceinline__ void ldm_x2_trans(unsigned& r0, unsigned& r1, unsigned addr) {
    asm volatile("ldmatrix.sync.aligned.m8n8.x2.trans.shared.b16 {%0,%1}, [%2];"
                 : "=r"(r0), "=r"(r1) : "r"(addr));
}
__device__ __forceinline__ void mma_bf16(float* c, const unsigned* a, const unsigned* b) {
    asm volatile(
        "mma.sync.aligned.m16n8k16.row.col.f32.bf16.bf16.f32 "
        "{%0,%1,%2,%3}, {%4,%5,%6,%7}, {%8,%9}, {%0,%1,%2,%3};"
        : "+f"(c[0]), "+f"(c[1]), "+f"(c[2]), "+f"(c[3])
        : "r"(a[0]), "r"(a[1]), "r"(a[2]), "r"(a[3]), "r"(b[0]), "r"(b[1]));
}

// Split 8 fp32 values into (hi, mid) bf16 planes packed as uint4 each.
__device__ __forceinline__ void split8(const float* xs, uint4& hq, uint4& mq) {
    unsigned h[4], m[4];
#pragma unroll
    for (int i = 0; i < 4; i++) {
        __nv_bfloat162 h2, m2;
        {
            const float x = xs[2 * i];
            const __nv_bfloat16 hi = __float2bfloat16(x);
            h2.x = hi; m2.x = __float2bfloat16(x - __bfloat162float(hi));
        }
        {
            const float x = xs[2 * i + 1];
            const __nv_bfloat16 hi = __float2bfloat16(x);
            h2.y = hi; m2.y = __float2bfloat16(x - __bfloat162float(hi));
        }
        h[i] = *(unsigned*)&h2;
        m[i] = *(unsigned*)&m2;
    }
    hq = make_uint4(h[0], h[1], h[2], h[3]);
    mq = make_uint4(m[0], m[1], m[2], m[3]);
}

__global__ __launch_bounds__(256) void xu_gemm_mma_kernel(
    const float* __restrict__ X,     // [B*T, D]
    const float* __restrict__ bias)  // [K]
{
    // [stage][plane] double-buffered tiles
    __shared__ __nv_bfloat16 sA[2][2][128][SA_STRIDE];
    __shared__ __nv_bfloat16 sB[2][2][GBK][SB_STRIDE];

    const int m0 = blockIdx.x * 128;
    const int n0 = blockIdx.y * 128;
    const int tid = (int)threadIdx.x;
    const int lane = tid & 31;
    const int wid = tid >> 5;
    const int wm = (wid >> 1) * 32;     // warp M offset 0/32/64/96
    const int wn = (wid & 1) * 64;      // warp N offset 0/64

    // X stage mapping: row = tid>>1 (0..127), colgroup = (tid&1)*8
    const int xa_row = tid >> 1;
    const int xa_cg  = (tid & 1) * 8;
    // U stage mapping: krow = tid>>4 (0..15), ncol8 = (tid&15)*8
    const int ub_k   = tid >> 4;
    const int ub_n   = (tid & 15) * 8;

    float c[2][8][4];
#pragma unroll
    for (int mt = 0; mt < 2; mt++)
#pragma unroll
        for (int nt = 0; nt < 8; nt++)
#pragma unroll
            for (int q = 0; q < 4; q++) c[mt][nt][q] = 0.0f;

    // ldmatrix lane addressing
    const int lq  = lane >> 3;
    const int lr  = lane & 7;
    const int a_r = (lq & 1) * 8 + lr;      // + mt*16 + wm
    const int a_k = (lq >> 1) * 8;
    const int bl  = lane & 15;
    const int b_k = (bl >> 3) * 8 + (bl & 7);

    const float* xrow = &X[(size_t)(m0 + xa_row) * D_];

    // ---- prologue: stage 0 ----
    {
        const float4 xv0 = *(const float4*)&xrow[xa_cg];
        const float4 xv1 = *(const float4*)&xrow[xa_cg + 4];
        float xs[8] = {xv0.x, xv0.y, xv0.z, xv0.w, xv1.x, xv1.y, xv1.z, xv1.w};
        uint4 hq, mq;
        split8(xs, hq, mq);
        *(uint4*)&sA[0][0][xa_row][xa_cg] = hq;
        *(uint4*)&sA[0][1][xa_row][xa_cg] = mq;

        const size_t uoff = (size_t)ub_k * K_ + (n0 + ub_n);
        cp_async16(&sB[0][0][ub_k][ub_n], &g_Uhi[uoff]);
        cp_async16(&sB[0][1][ub_k][ub_n], &g_Umid[uoff]);
        cp_commit();
    }
    cp_wait_all();
    __syncthreads();

    for (int iter = 0; iter < D_ / GBK; iter++) {
        const int cur = iter & 1;
        const int nxt = cur ^ 1;
        const bool more = (iter + 1) < (D_ / GBK);

        // ---- prefetch next stage: U via cp.async, X via LDG (overlaps mma) ----
        float xs[8];
        if (more) {
            const int k0n = (iter + 1) * GBK;
            const float4 xv0 = *(const float4*)&xrow[k0n + xa_cg];
            const float4 xv1 = *(const float4*)&xrow[k0n + xa_cg + 4];
            xs[0] = xv0.x; xs[1] = xv0.y; xs[2] = xv0.z; xs[3] = xv0.w;
            xs[4] = xv1.x; xs[5] = xv1.y; xs[6] = xv1.z; xs[7] = xv1.w;
            const size_t uoff = (size_t)(k0n + ub_k) * K_ + (n0 + ub_n);
            cp_async16(&sB[nxt][0][ub_k][ub_n], &g_Uhi[uoff]);
            cp_async16(&sB[nxt][1][ub_k][ub_n], &g_Umid[uoff]);
            cp_commit();
        }

        // ---- A fragments from current stage: [mt][plane][4] ----
        unsigned afr[2][2][4];
#pragma unroll
        for (int mt = 0; mt < 2; mt++) {
            const int row = wm + mt * 16 + a_r;
#pragma unroll
            for (int p = 0; p < 2; p++) {
                const unsigned addr = smem_u32(&sA[cur][p][row][a_k]);
                ldm_x4(afr[mt][p][0], afr[mt][p][1], afr[mt][p][2], afr[mt][p][3], addr);
            }
        }

        // ---- n8 tiles: 3 mma terms each ----
#pragma unroll
        for (int nt = 0; nt < 8; nt++) {
            unsigned bfr[2][2];
#pragma unroll
            for (int p = 0; p < 2; p++) {
                const unsigned addr = smem_u32(&sB[cur][p][b_k][wn + nt * 8]);
                ldm_x2_trans(bfr[p][0], bfr[p][1], addr);
            }
#pragma unroll
            for (int mt = 0; mt < 2; mt++) {
                mma_bf16(c[mt][nt], afr[mt][0], bfr[0]);   // hi*hi
                mma_bf16(c[mt][nt], afr[mt][0], bfr[1]);   // hi*mid
                mma_bf16(c[mt][nt], afr[mt][1], bfr[0]);   // mid*hi
            }
        }

        // ---- commit X split into next stage, then fence the stage swap ----
        if (more) {
            uint4 hq, mq;
            split8(xs, hq, mq);
            *(uint4*)&sA[nxt][0][xa_row][xa_cg] = hq;
            *(uint4*)&sA[nxt][1][xa_row][xa_cg] = mq;
            cp_wait_all();
        }
        __syncthreads();
    }

    // ---- epilogue: add bias, store fp32 ----
    const int gid = lane >> 2;
    const int tig = lane & 3;
#pragma unroll
    for (int nt = 0; nt < 8; nt++) {
        const int col = n0 + wn + nt * 8 + 2 * tig;
        const float2 bv = *(const float2*)&bias[col];
#pragma unroll
        for (int mt = 0; mt < 2; mt++) {
            const size_t r0 = (size_t)(m0 + wm + mt * 16 + gid);
            float2 v0; v0.x = c[mt][nt][0] + bv.x; v0.y = c[mt][nt][1] + bv.y;
            float2 v1; v1.x = c[mt][nt][2] + bv.x; v1.y = c[mt][nt][3] + bv.y;
            *(float2*)&g_xu[r0 * K_ + col]       = v0;
            *(float2*)&g_xu[(r0 + 8) * K_ + col] = v1;
        }
    }
}

// =====================================================================
// Kernel 2: persistent per-batch recurrence, 512 threads/block (scalar,
// best-known R4 configuration: 741us). UNCHANGED.
// =====================================================================
#define RNN_SMEM_FLOATS (128 * 256 + 2 * 256 + 16 * 256)
#define RNN_SMEM_BYTES  (RNN_SMEM_FLOATS * 4)

__global__ __launch_bounds__(512, 1) void rnn_recurrence_kernel(
    const float* __restrict__ W,    // [K, K] row-major: W[j*K + k]
    float* __restrict__ out)        // [B, K]
{
    extern __shared__ float sm[];
    float* Wsm  = sm;                  // 128*256 floats
    float* hs0  = sm + 128 * 256;      // 256 floats: h for batch b0
    float* hs1  = hs0 + 256;           // 256 floats: h for batch b1
    float* part = hs1 + 256;           // 16*256 floats: part[(g*2+b)*256 + k]

    const int tid = (int)threadIdx.x;
    const int g   = tid >> 6;        // 0..7
    const int c   = tid & 63;        // 0..63
    const int col = c * 4;           // base column (k)
    const int b0  = blockIdx.x * 2;

    for (int i = tid; i < 128 * 64; i += 512) {
        const int row = i >> 6;
        const int c4  = (i & 63) * 4;
        *(float4*)&Wsm[row * 256 + c4] = *(const float4*)&W[row * 256 + c4];
    }
    float4 wreg[16];
#pragma unroll
    for (int jj = 0; jj < 16; jj++) {
        wreg[jj] = *(const float4*)&W[(128 + g * 16 + jj) * 256 + col];
    }
    if (tid < 256) { hs0[tid] = 0.0f; hs1[tid] = 0.0f; }
    __syncthreads();

    const int rb = tid >> 8;         // 0 or 1
    const int rk = tid & 255;        // 0..255
    const float* xup = g_xu + ((size_t)(b0 + rb) * T_) * K_ + rk;

    const int js = g * 16;
    float hn = 0.0f;

    for (int ts = 0; ts < T_; ts++) {
        const float xv = xup[(size_t)ts * K_];

        float4 acc0 = make_float4(0.f, 0.f, 0.f, 0.f);
        float4 acc1 = make_float4(0.f, 0.f, 0.f, 0.f);

#pragma unroll
        for (int jj = 0; jj < 16; jj += 4) {
            const float4 h0 = *(const float4*)&hs0[js + jj];
            const float4 h1 = *(const float4*)&hs1[js + jj];
            {
                const float4 w = *(const float4*)&Wsm[(js + jj + 0) * 256 + col];
                acc0.x = fmaf(w.x, h0.x, acc0.x); acc0.y = fmaf(w.y, h0.x, acc0.y);
                acc0.z = fmaf(w.z, h0.x, acc0.z); acc0.w = fmaf(w.w, h0.x, acc0.w);
                acc1.x = fmaf(w.x, h1.x, acc1.x); acc1.y = fmaf(w.y, h1.x, acc1.y);
                acc1.z = fmaf(w.z, h1.x, acc1.z); acc1.w = fmaf(w.w, h1.x, acc1.w);
            }
            {
                const float4 w = *(const float4*)&Wsm[(js + jj + 1) * 256 + col];
                acc0.x = fmaf(w.x, h0.y, acc0.x); acc0.y = fmaf(w.y, h0.y, acc0.y);
                acc0.z = fmaf(w.z, h0.y, acc0.z); acc0.w = fmaf(w.w, h0.y, acc0.w);
                acc1.x = fmaf(w.x, h1.y, acc1.x); acc1.y = fmaf(w.y, h1.y, acc1.y);
                acc1.z = fmaf(w.z, h1.y, acc1.z); acc1.w = fmaf(w.w, h1.y, acc1.w);
            }
            {
                const float4 w = *(const float4*)&Wsm[(js + jj + 2) * 256 + col];
                acc0.x = fmaf(w.x, h0.z, acc0.x); acc0.y = fmaf(w.y, h0.z, acc0.y);
                acc0.z = fmaf(w.z, h0.z, acc0.z); acc0.w = fmaf(w.w, h0.z, acc0.w);
                acc1.x = fmaf(w.x, h1.z, acc1.x); acc1.y = fmaf(w.y, h1.z, acc1.y);
                acc1.z = fmaf(w.z, h1.z, acc1.z); acc1.w = fmaf(w.w, h1.z, acc1.w);
            }
            {
                const float4 w = *(const float4*)&Wsm[(js + jj + 3) * 256 + col];
                acc0.x = fmaf(w.x, h0.w, acc0.x); acc0.y = fmaf(w.y, h0.w, acc0.y);
                acc0.z = fmaf(w.z, h0.w, acc0.z); acc0.w = fmaf(w.w, h0.w, acc0.w);
                acc1.x = fmaf(w.x, h1.w, acc1.x); acc1.y = fmaf(w.y, h1.w, acc1.y);
                acc1.z = fmaf(w.z, h1.w, acc1.z); acc1.w = fmaf(w.w, h1.w, acc1.w);
            }
        }
#pragma unroll
        for (int jj = 0; jj < 16; jj += 4) {
            const float4 h0 = *(const float4*)&hs0[128 + js + jj];
            const float4 h1 = *(const float4*)&hs1[128 + js + jj];
            {
                const float4 w = wreg[jj + 0];
                acc0.x = fmaf(w.x, h0.x, acc0.x); acc0.y = fmaf(w.y, h0.x, acc0.y);
                acc0.z = fmaf(w.z, h0.x, acc0.z); acc0.w = fmaf(w.w, h0.x, acc0.w);
                acc1.x = fmaf(w.x, h1.x, acc1.x); acc1.y = fmaf(w.y, h1.x, acc1.y);
                acc1.z = fmaf(w.z, h1.x, acc1.z); acc1.w = fmaf(w.w, h1.x, acc1.w);
            }
            {
                const float4 w = wreg[jj + 1];
                acc0.x = fmaf(w.x, h0.y, acc0.x); acc0.y = fmaf(w.y, h0.y, acc0.y);
                acc0.z = fmaf(w.z, h0.y, acc0.z); acc0.w = fmaf(w.w, h0.y, acc0.w);
                acc1.x = fmaf(w.x, h1.y, acc1.x); acc1.y = fmaf(w.y, h1.y, acc1.y);
                acc1.z = fmaf(w.z, h1.y, acc1.z); acc1.w = fmaf(w.w, h1.y, acc1.w);
            }
            {
                const float4 w = wreg[jj + 2];
                acc0.x = fmaf(w.x, h0.z, acc0.x); acc0.y = fmaf(w.y, h0.z, acc0.y);
                acc0.z = fmaf(w.z, h0.z, acc0.z); acc0.w = fmaf(w.w, h0.z, acc0.w);
                acc1.x = fmaf(w.x, h1.z, acc1.x); acc1.y = fmaf(w.y, h1.z, acc1.y);
                acc1.z = fmaf(w.z, h1.z, acc1.z); acc1.w = fmaf(w.w, h1.z, acc1.w);
            }
            {
                const float4 w = wreg[jj + 3];
                acc0.x = fmaf(w.x, h0.w, acc0.x); acc0.y = fmaf(w.y, h0.w, acc0.y);
                acc0.z = fmaf(w.z, h0.w, acc0.z); acc0.w = fmaf(w.w, h0.w, acc0.w);
                acc1.x = fmaf(w.x, h1.w, acc1.x); acc1.y = fmaf(w.y, h1.w, acc1.y);
                acc1.z = fmaf(w.z, h1.w, acc1.z); acc1.w = fmaf(w.w, h1.w, acc1.w);
            }
        }

        *(float4*)&part[(g * 2 + 0) * 256 + col] = acc0;
        *(float4*)&part[(g * 2 + 1) * 256 + col] = acc1;
        __syncthreads();

        float s = 0.0f;
#pragma unroll
        for (int gg = 0; gg < 8; gg++) s += part[(gg * 2 + rb) * 256 + rk];

        hn = tanhf(xv + s);
        if (rb == 0) hs0[rk] = hn; else hs1[rk] = hn;
        __syncthreads();
    }

    out[(size_t)(b0 + rb) * K_ + rk] = hn;
}

// =====================================================================
// Harness entry
// metadata order: inputs [B,T,D] f32, U [D,K] f32, W [K,K] f32, b [K] f32
// output: [B,1,K] f32
// =====================================================================
extern "C" void kernel_launch(void* const* d_in, const int* in_sizes, int n_in,
                              void* d_out, int out_size) {
    const float* X    = (const float*)d_in[0];
    const float* U    = (const float*)d_in[1];
    const float* W    = (const float*)d_in[2];
    const float* bias = (const float*)d_in[3];
    float* out = (float*)d_out;

    cudaError_t attr_rc = cudaFuncSetAttribute(
        rnn_recurrence_kernel,
        cudaFuncAttributeMaxDynamicSharedMemorySize,
        RNN_SMEM_BYTES);
    (void)attr_rc;

    u_split_kernel<<<D_ * K_ / 256, 256>>>(U);

    dim3 gemm_grid(B_ * T_ / 128, K_ / 128);   // (1024, 2)
    xu_gemm_mma_kernel<<<gemm_grid, 256>>>(X, bias);

    rnn_recurrence_kernel<<<128, 512, RNN_SMEM_BYTES>>>(W, out);
}

// round 14
// speedup vs baseline: 1.3129x; 1.0180x over previous
#include <cuda_runtime.h>
#include <cuda_bf16.h>
#include <cstdint>
#include <math.h>

#define B_   256
#define T_   512
#define D_   256
#define K_   256

// Scratch: precomputed input projection xU [B, T, K] (134 MB).
__device__ float g_xu[(size_t)B_ * T_ * K_];
// U split into 2 bf16 planes (hi, mid): 16 mantissa bits total.
__device__ __nv_bfloat16 g_Uhi[D_ * K_];
__device__ __nv_bfloat16 g_Umid[D_ * K_];

// =====================================================================
// Kernel 0: split U into 2 bf16 planes.
// =====================================================================
__global__ void u_split_kernel(const float* __restrict__ U) {
    const int i = blockIdx.x * 256 + threadIdx.x;
    const float x = U[i];
    const __nv_bfloat16 hi = __float2bfloat16(x);
    const float r1 = x - __bfloat162float(hi);
    g_Uhi[i]  = hi;
    g_Umid[i] = __float2bfloat16(r1);
}

// =====================================================================
// Kernel 1: xU = X @ U + b via bf16 mma.sync, 2-plane split, 3 terms:
//   x*u ~= xh*uh + xh*um + xm*uh      (drops ~2^-16-relative terms)
// Block tile 128(M) x 128(N), BK=16, 256 threads = 8 warps (4Mx2N).
// Double-buffered smem; U planes staged via cp.async; X staged via
// LDG->split->STS overlapped with the current stage's mma work.
// (R11 configuration, measured 175us == fallback-HMMA pipe roofline.)
// =====================================================================
#define GBK 16
#define SA_STRIDE 24    // bf16 elems per row (48B, 16B-aligned)
#define SB_STRIDE 136   // bf16 elems per row (272B, 16B-aligned)

__device__ __forceinline__ unsigned smem_u32(const void* p) {
    return (unsigned)__cvta_generic_to_shared(p);
}
__device__ __forceinline__ void cp_async16(void* dst, const void* src) {
    asm volatile("cp.async.ca.shared.global [%0], [%1], 16;"
                 :: "r"(smem_u32(dst)), "l"(src));
}
__device__ __forceinline__ void cp_commit() {
    asm volatile("cp.async.commit_group;");
}
__device__ __forceinline__ void cp_wait_all() {
    asm volatile("cp.async.wait_group 0;");
}

__device__ __forceinline__ void ldm_x4(unsigned& r0, unsigned& r1, unsigned& r2, unsigned& r3, unsigned addr) {
    asm volatile("ldmatrix.sync.aligned.m8n8.x4.shared.b16 {%0,%1,%2,%3}, [%4];"
                 : "=r"(r0), "=r"(r1), "=r"(r2), "=r"(r3) : "r"(addr));
}
__device__ __forceinline__ void ldm_x2_trans(unsigned& r0, unsigned& r1, unsigned addr) {
    asm volatile("ldmatrix.sync.aligned.m8n8.x2.trans.shared.b16 {%0,%1}, [%2];"
                 : "=r"(r0), "=r"(r1) : "r"(addr));
}
__device__ __forceinline__ void mma_bf16(float* c, const unsigned* a, const unsigned* b) {
    asm volatile(
        "mma.sync.aligned.m16n8k16.row.col.f32.bf16.bf16.f32 "
        "{%0,%1,%2,%3}, {%4,%5,%6,%7}, {%8,%9}, {%0,%1,%2,%3};"
        : "+f"(c[0]), "+f"(c[1]), "+f"(c[2]), "+f"(c[3])
        : "r"(a[0]), "r"(a[1]), "r"(a[2]), "r"(a[3]), "r"(b[0]), "r"(b[1]));
}

// Split 8 fp32 values into (hi, mid) bf16 planes packed as uint4 each.
__device__ __forceinline__ void split8(const float* xs, uint4& hq, uint4& mq) {
    unsigned h[4], m[4];
#pragma unroll
    for (int i = 0; i < 4; i++) {
        __nv_bfloat162 h2, m2;
        {
            const float x = xs[2 * i];
            const __nv_bfloat16 hi = __float2bfloat16(x);
            h2.x = hi; m2.x = __float2bfloat16(x - __bfloat162float(hi));
        }
        {
            const float x = xs[2 * i + 1];
            const __nv_bfloat16 hi = __float2bfloat16(x);
            h2.y = hi; m2.y = __float2bfloat16(x - __bfloat162float(hi));
        }
        h[i] = *(unsigned*)&h2;
        m[i] = *(unsigned*)&m2;
    }
    hq = make_uint4(h[0], h[1], h[2], h[3]);
    mq = make_uint4(m[0], m[1], m[2], m[3]);
}

__global__ __launch_bounds__(256) void xu_gemm_mma_kernel(
    const float* __restrict__ X,     // [B*T, D]
    const float* __restrict__ bias)  // [K]
{
    // [stage][plane] double-buffered tiles
    __shared__ __nv_bfloat16 sA[2][2][128][SA_STRIDE];
    __shared__ __nv_bfloat16 sB[2][2][GBK][SB_STRIDE];

    const int m0 = blockIdx.x * 128;
    const int n0 = blockIdx.y * 128;
    const int tid = (int)threadIdx.x;
    const int lane = tid & 31;
    const int wid = tid >> 5;
    const int wm = (wid >> 1) * 32;     // warp M offset 0/32/64/96
    const int wn = (wid & 1) * 64;      // warp N offset 0/64

    // X stage mapping: row = tid>>1 (0..127), colgroup = (tid&1)*8
    const int xa_row = tid >> 1;
    const int xa_cg  = (tid & 1) * 8;
    // U stage mapping: krow = tid>>4 (0..15), ncol8 = (tid&15)*8
    const int ub_k   = tid >> 4;
    const int ub_n   = (tid & 15) * 8;

    float c[2][8][4];
#pragma unroll
    for (int mt = 0; mt < 2; mt++)
#pragma unroll
        for (int nt = 0; nt < 8; nt++)
#pragma unroll
            for (int q = 0; q < 4; q++) c[mt][nt][q] = 0.0f;

    // ldmatrix lane addressing
    const int lq  = lane >> 3;
    const int lr  = lane & 7;
    const int a_r = (lq & 1) * 8 + lr;      // + mt*16 + wm
    const int a_k = (lq >> 1) * 8;
    const int bl  = lane & 15;
    const int b_k = (bl >> 3) * 8 + (bl & 7);

    const float* xrow = &X[(size_t)(m0 + xa_row) * D_];

    // ---- prologue: stage 0 ----
    {
        const float4 xv0 = *(const float4*)&xrow[xa_cg];
        const float4 xv1 = *(const float4*)&xrow[xa_cg + 4];
        float xs[8] = {xv0.x, xv0.y, xv0.z, xv0.w, xv1.x, xv1.y, xv1.z, xv1.w};
        uint4 hq, mq;
        split8(xs, hq, mq);
        *(uint4*)&sA[0][0][xa_row][xa_cg] = hq;
        *(uint4*)&sA[0][1][xa_row][xa_cg] = mq;

        const size_t uoff = (size_t)ub_k * K_ + (n0 + ub_n);
        cp_async16(&sB[0][0][ub_k][ub_n], &g_Uhi[uoff]);
        cp_async16(&sB[0][1][ub_k][ub_n], &g_Umid[uoff]);
        cp_commit();
    }
    cp_wait_all();
    __syncthreads();

    for (int iter = 0; iter < D_ / GBK; iter++) {
        const int cur = iter & 1;
        const int nxt = cur ^ 1;
        const bool more = (iter + 1) < (D_ / GBK);

        // ---- prefetch next stage: U via cp.async, X via LDG (overlaps mma) ----
        float xs[8];
        if (more) {
            const int k0n = (iter + 1) * GBK;
            const float4 xv0 = *(const float4*)&xrow[k0n + xa_cg];
            const float4 xv1 = *(const float4*)&xrow[k0n + xa_cg + 4];
            xs[0] = xv0.x; xs[1] = xv0.y; xs[2] = xv0.z; xs[3] = xv0.w;
            xs[4] = xv1.x; xs[5] = xv1.y; xs[6] = xv1.z; xs[7] = xv1.w;
            const size_t uoff = (size_t)(k0n + ub_k) * K_ + (n0 + ub_n);
            cp_async16(&sB[nxt][0][ub_k][ub_n], &g_Uhi[uoff]);
            cp_async16(&sB[nxt][1][ub_k][ub_n], &g_Umid[uoff]);
            cp_commit();
        }

        // ---- A fragments from current stage: [mt][plane][4] ----
        unsigned afr[2][2][4];
#pragma unroll
        for (int mt = 0; mt < 2; mt++) {
            const int row = wm + mt * 16 + a_r;
#pragma unroll
            for (int p = 0; p < 2; p++) {
                const unsigned addr = smem_u32(&sA[cur][p][row][a_k]);
                ldm_x4(afr[mt][p][0], afr[mt][p][1], afr[mt][p][2], afr[mt][p][3], addr);
            }
        }

        // ---- n8 tiles: 3 mma terms each ----
#pragma unroll
        for (int nt = 0; nt < 8; nt++) {
            unsigned bfr[2][2];
#pragma unroll
            for (int p = 0; p < 2; p++) {
                const unsigned addr = smem_u32(&sB[cur][p][b_k][wn + nt * 8]);
                ldm_x2_trans(bfr[p][0], bfr[p][1], addr);
            }
#pragma unroll
            for (int mt = 0; mt < 2; mt++) {
                mma_bf16(c[mt][nt], afr[mt][0], bfr[0]);   // hi*hi
                mma_bf16(c[mt][nt], afr[mt][0], bfr[1]);   // hi*mid
                mma_bf16(c[mt][nt], afr[mt][1], bfr[0]);   // mid*hi
            }
        }

        // ---- commit X split into next stage, then fence the stage swap ----
        if (more) {
            uint4 hq, mq;
            split8(xs, hq, mq);
            *(uint4*)&sA[nxt][0][xa_row][xa_cg] = hq;
            *(uint4*)&sA[nxt][1][xa_row][xa_cg] = mq;
            cp_wait_all();
        }
        __syncthreads();
    }

    // ---- epilogue: add bias, store fp32 ----
    const int gid = lane >> 2;
    const int tig = lane & 3;
#pragma unroll
    for (int nt = 0; nt < 8; nt++) {
        const int col = n0 + wn + nt * 8 + 2 * tig;
        const float2 bv = *(const float2*)&bias[col];
#pragma unroll
        for (int mt = 0; mt < 2; mt++) {
            const size_t r0 = (size_t)(m0 + wm + mt * 16 + gid);
            float2 v0; v0.x = c[mt][nt][0] + bv.x; v0.y = c[mt][nt][1] + bv.y;
            float2 v1; v1.x = c[mt][nt][2] + bv.x; v1.y = c[mt][nt][3] + bv.y;
            *(float2*)&g_xu[r0 * K_ + col]       = v0;
            *(float2*)&g_xu[(r0 + 8) * K_ + col] = v1;
        }
    }
}

// =====================================================================
// Kernel 2: persistent per-batch recurrence, 512 threads/block.
// R4 structure (measured 741us) + HW tanh (MUFU.TANH) replacing tanhf
// on the serial reduce->publish critical path.
// =====================================================================
#define RNN_SMEM_FLOATS (128 * 256 + 2 * 256 + 16 * 256)
#define RNN_SMEM_BYTES  (RNN_SMEM_FLOATS * 4)

__device__ __forceinline__ float tanh_fast(float x) {
    float y;
    asm("tanh.approx.f32 %0, %1;" : "=f"(y) : "f"(x));
    return y;
}

__global__ __launch_bounds__(512, 1) void rnn_recurrence_kernel(
    const float* __restrict__ W,    // [K, K] row-major: W[j*K + k]
    float* __restrict__ out)        // [B, K]
{
    extern __shared__ float sm[];
    float* Wsm  = sm;                  // 128*256 floats
    float* hs0  = sm + 128 * 256;      // 256 floats: h for batch b0
    float* hs1  = hs0 + 256;           // 256 floats: h for batch b1
    float* part = hs1 + 256;           // 16*256 floats: part[(g*2+b)*256 + k]

    const int tid = (int)threadIdx.x;
    const int g   = tid >> 6;        // 0..7
    const int c   = tid & 63;        // 0..63
    const int col = c * 4;           // base column (k)
    const int b0  = blockIdx.x * 2;

    for (int i = tid; i < 128 * 64; i += 512) {
        const int row = i >> 6;
        const int c4  = (i & 63) * 4;
        *(float4*)&Wsm[row * 256 + c4] = *(const float4*)&W[row * 256 + c4];
    }
    float4 wreg[16];
#pragma unroll
    for (int jj = 0; jj < 16; jj++) {
        wreg[jj] = *(const float4*)&W[(128 + g * 16 + jj) * 256 + col];
    }
    if (tid < 256) { hs0[tid] = 0.0f; hs1[tid] = 0.0f; }
    __syncthreads();

    const int rb = tid >> 8;         // 0 or 1
    const int rk = tid & 255;        // 0..255
    const float* xup = g_xu + ((size_t)(b0 + rb) * T_) * K_ + rk;

    const int js = g * 16;
    float hn = 0.0f;

    for (int ts = 0; ts < T_; ts++) {
        const float xv = xup[(size_t)ts * K_];

        float4 acc0 = make_float4(0.f, 0.f, 0.f, 0.f);
        float4 acc1 = make_float4(0.f, 0.f, 0.f, 0.f);

#pragma unroll
        for (int jj = 0; jj < 16; jj += 4) {
            const float4 h0 = *(const float4*)&hs0[js + jj];
            const float4 h1 = *(const float4*)&hs1[js + jj];
            {
                const float4 w = *(const float4*)&Wsm[(js + jj + 0) * 256 + col];
                acc0.x = fmaf(w.x, h0.x, acc0.x); acc0.y = fmaf(w.y, h0.x, acc0.y);
                acc0.z = fmaf(w.z, h0.x, acc0.z); acc0.w = fmaf(w.w, h0.x, acc0.w);
                acc1.x = fmaf(w.x, h1.x, acc1.x); acc1.y = fmaf(w.y, h1.x, acc1.y);
                acc1.z = fmaf(w.z, h1.x, acc1.z); acc1.w = fmaf(w.w, h1.x, acc1.w);
            }
            {
                const float4 w = *(const float4*)&Wsm[(js + jj + 1) * 256 + col];
                acc0.x = fmaf(w.x, h0.y, acc0.x); acc0.y = fmaf(w.y, h0.y, acc0.y);
                acc0.z = fmaf(w.z, h0.y, acc0.z); acc0.w = fmaf(w.w, h0.y, acc0.w);
                acc1.x = fmaf(w.x, h1.y, acc1.x); acc1.y = fmaf(w.y, h1.y, acc1.y);
                acc1.z = fmaf(w.z, h1.y, acc1.z); acc1.w = fmaf(w.w, h1.y, acc1.w);
            }
            {
                const float4 w = *(const float4*)&Wsm[(js + jj + 2) * 256 + col];
                acc0.x = fmaf(w.x, h0.z, acc0.x); acc0.y = fmaf(w.y, h0.z, acc0.y);
                acc0.z = fmaf(w.z, h0.z, acc0.z); acc0.w = fmaf(w.w, h0.z, acc0.w);
                acc1.x = fmaf(w.x, h1.z, acc1.x); acc1.y = fmaf(w.y, h1.z, acc1.y);
                acc1.z = fmaf(w.z, h1.z, acc1.z); acc1.w = fmaf(w.w, h1.z, acc1.w);
            }
            {
                const float4 w = *(const float4*)&Wsm[(js + jj + 3) * 256 + col];
                acc0.x = fmaf(w.x, h0.w, acc0.x); acc0.y = fmaf(w.y, h0.w, acc0.y);
                acc0.z = fmaf(w.z, h0.w, acc0.z); acc0.w = fmaf(w.w, h0.w, acc0.w);
                acc1.x = fmaf(w.x, h1.w, acc1.x); acc1.y = fmaf(w.y, h1.w, acc1.y);
                acc1.z = fmaf(w.z, h1.w, acc1.z); acc1.w = fmaf(w.w, h1.w, acc1.w);
            }
        }
#pragma unroll
        for (int jj = 0; jj < 16; jj += 4) {
            const float4 h0 = *(const float4*)&hs0[128 + js + jj];
            const float4 h1 = *(const float4*)&hs1[128 + js + jj];
            {
                const float4 w = wreg[jj + 0];
                acc0.x = fmaf(w.x, h0.x, acc0.x); acc0.y = fmaf(w.y, h0.x, acc0.y);
                acc0.z = fmaf(w.z, h0.x, acc0.z); acc0.w = fmaf(w.w, h0.x, acc0.w);
                acc1.x = fmaf(w.x, h1.x, acc1.x); acc1.y = fmaf(w.y, h1.x, acc1.y);
                acc1.z = fmaf(w.z, h1.x, acc1.z); acc1.w = fmaf(w.w, h1.x, acc1.w);
            }
            {
                const float4 w = wreg[jj + 1];
                acc0.x = fmaf(w.x, h0.y, acc0.x); acc0.y = fmaf(w.y, h0.y, acc0.y);
                acc0.z = fmaf(w.z, h0.y, acc0.z); acc0.w = fmaf(w.w, h0.y, acc0.w);
                acc1.x = fmaf(w.x, h1.y, acc1.x); acc1.y = fmaf(w.y, h1.y, acc1.y);
                acc1.z = fmaf(w.z, h1.y, acc1.z); acc1.w = fmaf(w.w, h1.y, acc1.w);
            }
            {
                const float4 w = wreg[jj + 2];
                acc0.x = fmaf(w.x, h0.z, acc0.x); acc0.y = fmaf(w.y, h0.z, acc0.y);
                acc0.z = fmaf(w.z, h0.z, acc0.z); acc0.w = fmaf(w.w, h0.z, acc0.w);
                acc1.x = fmaf(w.x, h1.z, acc1.x); acc1.y = fmaf(w.y, h1.z, acc1.y);
                acc1.z = fmaf(w.z, h1.z, acc1.z); acc1.w = fmaf(w.w, h1.z, acc1.w);
            }
            {
                const float4 w = wreg[jj + 3];
                acc0.x = fmaf(w.x, h0.w, acc0.x); acc0.y = fmaf(w.y, h0.w, acc0.y);
                acc0.z = fmaf(w.z, h0.w, acc0.z); acc0.w = fmaf(w.w, h0.w, acc0.w);
                acc1.x = fmaf(w.x, h1.w, acc1.x); acc1.y = fmaf(w.y, h1.w, acc1.y);
                acc1.z = fmaf(w.z, h1.w, acc1.z); acc1.w = fmaf(w.w, h1.w, acc1.w);
            }
        }

        *(float4*)&part[(g * 2 + 0) * 256 + col] = acc0;
        *(float4*)&part[(g * 2 + 1) * 256 + col] = acc1;
        __syncthreads();

        float s = 0.0f;
#pragma unroll
        for (int gg = 0; gg < 8; gg++) s += part[(gg * 2 + rb) * 256 + rk];

        hn = tanh_fast(xv + s);
        if (rb == 0) hs0[rk] = hn; else hs1[rk] = hn;
        __syncthreads();
    }

    out[(size_t)(b0 + rb) * K_ + rk] = hn;
}

// =====================================================================
// Harness entry
// metadata order: inputs [B,T,D] f32, U [D,K] f32, W [K,K] f32, b [K] f32
// output: [B,1,K] f32
// =====================================================================
extern "C" void kernel_launch(void* const* d_in, const int* in_sizes, int n_in,
                              void* d_out, int out_size) {
    const float* X    = (const float*)d_in[0];
    const float* U    = (const float*)d_in[1];
    const float* W    = (const float*)d_in[2];
    const float* bias = (const float*)d_in[3];
    float* out = (float*)d_out;

    cudaError_t attr_rc = cudaFuncSetAttribute(
        rnn_recurrence_kernel,
        cudaFuncAttributeMaxDynamicSharedMemorySize,
        RNN_SMEM_BYTES);
    (void)attr_rc;

    u_split_kernel<<<D_ * K_ / 256, 256>>>(U);

    dim3 gemm_grid(B_ * T_ / 128, K_ / 128);   // (1024, 2)
    xu_gemm_mma_kernel<<<gemm_grid, 256>>>(X, bias);

    rnn_recurrence_kernel<<<128, 512, RNN_SMEM_BYTES>>>(W, out);
}

// round 16
// speedup vs baseline: 1.3379x; 1.0191x over previous
#include <cuda_runtime.h>
#include <cuda_bf16.h>
#include <cstdint>
#include <math.h>

#define B_   256
#define T_   512
#define D_   256
#define K_   256

// Scratch: precomputed input projection xU [B, T, K] (134 MB).
__device__ float g_xu[(size_t)B_ * T_ * K_];
// U split into 2 bf16 planes (hi, mid): 16 mantissa bits total.
__device__ __nv_bfloat16 g_Uhi[D_ * K_];
__device__ __nv_bfloat16 g_Umid[D_ * K_];

// =====================================================================
// Kernel 0: split U into 2 bf16 planes.
// =====================================================================
__global__ void u_split_kernel(const float* __restrict__ U) {
    const int i = blockIdx.x * 256 + threadIdx.x;
    const float x = U[i];
    const __nv_bfloat16 hi = __float2bfloat16(x);
    const float r1 = x - __bfloat162float(hi);
    g_Uhi[i]  = hi;
    g_Umid[i] = __float2bfloat16(r1);
}

// =====================================================================
// Kernel 1: xU = X @ U + b via bf16 mma.sync, 2-plane split, 3 terms.
// (R11/R14 configuration, measured 175us == fallback-HMMA roofline.)
// =====================================================================
#define GBK 16
#define SA_STRIDE 24
#define SB_STRIDE 136

__device__ __forceinline__ unsigned smem_u32(const void* p) {
    return (unsigned)__cvta_generic_to_shared(p);
}
__device__ __forceinline__ void cp_async16(void* dst, const void* src) {
    asm volatile("cp.async.ca.shared.global [%0], [%1], 16;"
                 :: "r"(smem_u32(dst)), "l"(src));
}
__device__ __forceinline__ void cp_commit() {
    asm volatile("cp.async.commit_group;");
}
__device__ __forceinline__ void cp_wait_all() {
    asm volatile("cp.async.wait_group 0;");
}

__device__ __forceinline__ void ldm_x4(unsigned& r0, unsigned& r1, unsigned& r2, unsigned& r3, unsigned addr) {
    asm volatile("ldmatrix.sync.aligned.m8n8.x4.shared.b16 {%0,%1,%2,%3}, [%4];"
                 : "=r"(r0), "=r"(r1), "=r"(r2), "=r"(r3) : "r"(addr));
}
__device__ __forceinline__ void ldm_x2_trans(unsigned& r0, unsigned& r1, unsigned addr) {
    asm volatile("ldmatrix.sync.aligned.m8n8.x2.trans.shared.b16 {%0,%1}, [%2];"
                 : "=r"(r0), "=r"(r1) : "r"(addr));
}
__device__ __forceinline__ void mma_bf16(float* c, const unsigned* a, const unsigned* b) {
    asm volatile(
        "mma.sync.aligned.m16n8k16.row.col.f32.bf16.bf16.f32 "
        "{%0,%1,%2,%3}, {%4,%5,%6,%7}, {%8,%9}, {%0,%1,%2,%3};"
        : "+f"(c[0]), "+f"(c[1]), "+f"(c[2]), "+f"(c[3])
        : "r"(a[0]), "r"(a[1]), "r"(a[2]), "r"(a[3]), "r"(b[0]), "r"(b[1]));
}

__device__ __forceinline__ void split8(const float* xs, uint4& hq, uint4& mq) {
    unsigned h[4], m[4];
#pragma unroll
    for (int i = 0; i < 4; i++) {
        __nv_bfloat162 h2, m2;
        {
            const float x = xs[2 * i];
            const __nv_bfloat16 hi = __float2bfloat16(x);
            h2.x = hi; m2.x = __float2bfloat16(x - __bfloat162float(hi));
        }
        {
            const float x = xs[2 * i + 1];
            const __nv_bfloat16 hi = __float2bfloat16(x);
            h2.y = hi; m2.y = __float2bfloat16(x - __bfloat162float(hi));
        }
        h[i] = *(unsigned*)&h2;
        m[i] = *(unsigned*)&m2;
    }
    hq = make_uint4(h[0], h[1], h[2], h[3]);
    mq = make_uint4(m[0], m[1], m[2], m[3]);
}

__global__ __launch_bounds__(256) void xu_gemm_mma_kernel(
    const float* __restrict__ X,     // [B*T, D]
    const float* __restrict__ bias)  // [K]
{
    __shared__ __nv_bfloat16 sA[2][2][128][SA_STRIDE];
    __shared__ __nv_bfloat16 sB[2][2][GBK][SB_STRIDE];

    const int m0 = blockIdx.x * 128;
    const int n0 = blockIdx.y * 128;
    const int tid = (int)threadIdx.x;
    const int lane = tid & 31;
    const int wid = tid >> 5;
    const int wm = (wid >> 1) * 32;
    const int wn = (wid & 1) * 64;

    const int xa_row = tid >> 1;
    const int xa_cg  = (tid & 1) * 8;
    const int ub_k   = tid >> 4;
    const int ub_n   = (tid & 15) * 8;

    float c[2][8][4];
#pragma unroll
    for (int mt = 0; mt < 2; mt++)
#pragma unroll
        for (int nt = 0; nt < 8; nt++)
#pragma unroll
            for (int q = 0; q < 4; q++) c[mt][nt][q] = 0.0f;

    const int lq  = lane >> 3;
    const int lr  = lane & 7;
    const int a_r = (lq & 1) * 8 + lr;
    const int a_k = (lq >> 1) * 8;
    const int bl  = lane & 15;
    const int b_k = (bl >> 3) * 8 + (bl & 7);

    const float* xrow = &X[(size_t)(m0 + xa_row) * D_];

    {
        const float4 xv0 = *(const float4*)&xrow[xa_cg];
        const float4 xv1 = *(const float4*)&xrow[xa_cg + 4];
        float xs[8] = {xv0.x, xv0.y, xv0.z, xv0.w, xv1.x, xv1.y, xv1.z, xv1.w};
        uint4 hq, mq;
        split8(xs, hq, mq);
        *(uint4*)&sA[0][0][xa_row][xa_cg] = hq;
        *(uint4*)&sA[0][1][xa_row][xa_cg] = mq;

        const size_t uoff = (size_t)ub_k * K_ + (n0 + ub_n);
        cp_async16(&sB[0][0][ub_k][ub_n], &g_Uhi[uoff]);
        cp_async16(&sB[0][1][ub_k][ub_n], &g_Umid[uoff]);
        cp_commit();
    }
    cp_wait_all();
    __syncthreads();

    for (int iter = 0; iter < D_ / GBK; iter++) {
        const int cur = iter & 1;
        const int nxt = cur ^ 1;
        const bool more = (iter + 1) < (D_ / GBK);

        float xs[8];
        if (more) {
            const int k0n = (iter + 1) * GBK;
            const float4 xv0 = *(const float4*)&xrow[k0n + xa_cg];
            const float4 xv1 = *(const float4*)&xrow[k0n + xa_cg + 4];
            xs[0] = xv0.x; xs[1] = xv0.y; xs[2] = xv0.z; xs[3] = xv0.w;
            xs[4] = xv1.x; xs[5] = xv1.y; xs[6] = xv1.z; xs[7] = xv1.w;
            const size_t uoff = (size_t)(k0n + ub_k) * K_ + (n0 + ub_n);
            cp_async16(&sB[nxt][0][ub_k][ub_n], &g_Uhi[uoff]);
            cp_async16(&sB[nxt][1][ub_k][ub_n], &g_Umid[uoff]);
            cp_commit();
        }

        unsigned afr[2][2][4];
#pragma unroll
        for (int mt = 0; mt < 2; mt++) {
            const int row = wm + mt * 16 + a_r;
#pragma unroll
            for (int p = 0; p < 2; p++) {
                const unsigned addr = smem_u32(&sA[cur][p][row][a_k]);
                ldm_x4(afr[mt][p][0], afr[mt][p][1], afr[mt][p][2], afr[mt][p][3], addr);
            }
        }

#pragma unroll
        for (int nt = 0; nt < 8; nt++) {
            unsigned bfr[2][2];
#pragma unroll
            for (int p = 0; p < 2; p++) {
                const unsigned addr = smem_u32(&sB[cur][p][b_k][wn + nt * 8]);
                ldm_x2_trans(bfr[p][0], bfr[p][1], addr);
            }
#pragma unroll
            for (int mt = 0; mt < 2; mt++) {
                mma_bf16(c[mt][nt], afr[mt][0], bfr[0]);   // hi*hi
                mma_bf16(c[mt][nt], afr[mt][0], bfr[1]);   // hi*mid
                mma_bf16(c[mt][nt], afr[mt][1], bfr[0]);   // mid*hi
            }
        }

        if (more) {
            uint4 hq, mq;
            split8(xs, hq, mq);
            *(uint4*)&sA[nxt][0][xa_row][xa_cg] = hq;
            *(uint4*)&sA[nxt][1][xa_row][xa_cg] = mq;
            cp_wait_all();
        }
        __syncthreads();
    }

    const int gid = lane >> 2;
    const int tig = lane & 3;
#pragma unroll
    for (int nt = 0; nt < 8; nt++) {
        const int col = n0 + wn + nt * 8 + 2 * tig;
        const float2 bv = *(const float2*)&bias[col];
#pragma unroll
        for (int mt = 0; mt < 2; mt++) {
            const size_t r0 = (size_t)(m0 + wm + mt * 16 + gid);
            float2 v0; v0.x = c[mt][nt][0] + bv.x; v0.y = c[mt][nt][1] + bv.y;
            float2 v1; v1.x = c[mt][nt][2] + bv.x; v1.y = c[mt][nt][3] + bv.y;
            *(float2*)&g_xu[r0 * K_ + col]       = v0;
            *(float2*)&g_xu[(r0 + 8) * K_ + col] = v1;
        }
    }
}

// =====================================================================
// Kernel 2: persistent per-batch recurrence, 1024 threads/block.
// 16 j-groups: group g covers smem rows [8g, 8g+8) and register rows
// [128+8g, 128+8g+8); 128 FFMA/thread/step. 8 warps/SMSP for latency
// hiding. Threads < 512 perform the reduce (16 partials) + tanh.
// =====================================================================
#define RNN_SMEM_FLOATS (128 * 256 + 2 * 256 + 32 * 256)
#define RNN_SMEM_BYTES  (RNN_SMEM_FLOATS * 4)

__device__ __forceinline__ float tanh_fast(float x) {
    float y;
    asm("tanh.approx.f32 %0, %1;" : "=f"(y) : "f"(x));
    return y;
}

__global__ __launch_bounds__(1024, 1) void rnn_recurrence_kernel(
    const float* __restrict__ W,    // [K, K] row-major: W[j*K + k]
    float* __restrict__ out)        // [B, K]
{
    extern __shared__ float sm[];
    float* Wsm  = sm;                  // 128*256 floats
    float* hs0  = sm + 128 * 256;      // 256 floats: h for batch b0
    float* hs1  = hs0 + 256;           // 256 floats: h for batch b1
    float* part = hs1 + 256;           // 32*256 floats: part[(g*2+b)*256 + k]

    const int tid = (int)threadIdx.x;
    const int g   = tid >> 6;        // 0..15
    const int c   = tid & 63;        // 0..63
    const int col = c * 4;           // base column (k)
    const int b0  = blockIdx.x * 2;

    // --- Load W rows 0..127 into smem (1024 threads x 8 float4) ---
    for (int i = tid; i < 128 * 64; i += 1024) {
        const int row = i >> 6;
        const int c4  = (i & 63) * 4;
        *(float4*)&Wsm[row * 256 + c4] = *(const float4*)&W[row * 256 + c4];
    }
    // --- W rows [128+8g, 128+8g+8) into registers for this thread's cols ---
    float4 wreg[8];
#pragma unroll
    for (int jj = 0; jj < 8; jj++) {
        wreg[jj] = *(const float4*)&W[(128 + g * 8 + jj) * 256 + col];
    }
    if (tid < 256) { hs0[tid] = 0.0f; hs1[tid] = 0.0f; }
    __syncthreads();

    // Reduce ownership: threads < 512 own (batch rb, column rk)
    const int rb = (tid >> 8) & 1;
    const int rk = tid & 255;
    const bool reducer = (tid < 512);
    const float* xup = g_xu + ((size_t)(b0 + rb) * T_) * K_ + rk;

    const int js = g * 8;
    float hn = 0.0f;

    for (int ts = 0; ts < T_; ts++) {
        float xv = 0.0f;
        if (reducer) xv = xup[(size_t)ts * K_];   // issued early, used after BAR1

        float4 acc0 = make_float4(0.f, 0.f, 0.f, 0.f);
        float4 acc1 = make_float4(0.f, 0.f, 0.f, 0.f);

        // smem W rows [8g, 8g+8)
#pragma unroll
        for (int jj = 0; jj < 8; jj += 4) {
            const float4 h0 = *(const float4*)&hs0[js + jj];
            const float4 h1 = *(const float4*)&hs1[js + jj];
            {
                const float4 w = *(const float4*)&Wsm[(js + jj + 0) * 256 + col];
                acc0.x = fmaf(w.x, h0.x, acc0.x); acc0.y = fmaf(w.y, h0.x, acc0.y);
                acc0.z = fmaf(w.z, h0.x, acc0.z); acc0.w = fmaf(w.w, h0.x, acc0.w);
                acc1.x = fmaf(w.x, h1.x, acc1.x); acc1.y = fmaf(w.y, h1.x, acc1.y);
                acc1.z = fmaf(w.z, h1.x, acc1.z); acc1.w = fmaf(w.w, h1.x, acc1.w);
            }
            {
                const float4 w = *(const float4*)&Wsm[(js + jj + 1) * 256 + col];
                acc0.x = fmaf(w.x, h0.y, acc0.x); acc0.y = fmaf(w.y, h0.y, acc0.y);
                acc0.z = fmaf(w.z, h0.y, acc0.z); acc0.w = fmaf(w.w, h0.y, acc0.w);
                acc1.x = fmaf(w.x, h1.y, acc1.x); acc1.y = fmaf(w.y, h1.y, acc1.y);
                acc1.z = fmaf(w.z, h1.y, acc1.z); acc1.w = fmaf(w.w, h1.y, acc1.w);
            }
            {
                const float4 w = *(const float4*)&Wsm[(js + jj + 2) * 256 + col];
                acc0.x = fmaf(w.x, h0.z, acc0.x); acc0.y = fmaf(w.y, h0.z, acc0.y);
                acc0.z = fmaf(w.z, h0.z, acc0.z); acc0.w = fmaf(w.w, h0.z, acc0.w);
                acc1.x = fmaf(w.x, h1.z, acc1.x); acc1.y = fmaf(w.y, h1.z, acc1.y);
                acc1.z = fmaf(w.z, h1.z, acc1.z); acc1.w = fmaf(w.w, h1.z, acc1.w);
            }
            {
                const float4 w = *(const float4*)&Wsm[(js + jj + 3) * 256 + col];
                acc0.x = fmaf(w.x, h0.w, acc0.x); acc0.y = fmaf(w.y, h0.w, acc0.y);
                acc0.z = fmaf(w.z, h0.w, acc0.z); acc0.w = fmaf(w.w, h0.w, acc0.w);
                acc1.x = fmaf(w.x, h1.w, acc1.x); acc1.y = fmaf(w.y, h1.w, acc1.y);
                acc1.z = fmaf(w.z, h1.w, acc1.z); acc1.w = fmaf(w.w, h1.w, acc1.w);
            }
        }
        // register W rows [128+8g, 128+8g+8)
#pragma unroll
        for (int jj = 0; jj < 8; jj += 4) {
            const float4 h0 = *(const float4*)&hs0[128 + js + jj];
            const float4 h1 = *(const float4*)&hs1[128 + js + jj];
            {
                const float4 w = wreg[jj + 0];
                acc0.x = fmaf(w.x, h0.x, acc0.x); acc0.y = fmaf(w.y, h0.x, acc0.y);
                acc0.z = fmaf(w.z, h0.x, acc0.z); acc0.w = fmaf(w.w, h0.x, acc0.w);
                acc1.x = fmaf(w.x, h1.x, acc1.x); acc1.y = fmaf(w.y, h1.x, acc1.y);
                acc1.z = fmaf(w.z, h1.x, acc1.z); acc1.w = fmaf(w.w, h1.x, acc1.w);
            }
            {
                const float4 w = wreg[jj + 1];
                acc0.x = fmaf(w.x, h0.y, acc0.x); acc0.y = fmaf(w.y, h0.y, acc0.y);
                acc0.z = fmaf(w.z, h0.y, acc0.z); acc0.w = fmaf(w.w, h0.y, acc0.w);
                acc1.x = fmaf(w.x, h1.y, acc1.x); acc1.y = fmaf(w.y, h1.y, acc1.y);
                acc1.z = fmaf(w.z, h1.y, acc1.z); acc1.w = fmaf(w.w, h1.y, acc1.w);
            }
            {
                const float4 w = wreg[jj + 2];
                acc0.x = fmaf(w.x, h0.z, acc0.x); acc0.y = fmaf(w.y, h0.z, acc0.y);
                acc0.z = fmaf(w.z, h0.z, acc0.z); acc0.w = fmaf(w.w, h0.z, acc0.w);
                acc1.x = fmaf(w.x, h1.z, acc1.x); acc1.y = fmaf(w.y, h1.z, acc1.y);
                acc1.z = fmaf(w.z, h1.z, acc1.z); acc1.w = fmaf(w.w, h1.z, acc1.w);
            }
            {
                const float4 w = wreg[jj + 3];
                acc0.x = fmaf(w.x, h0.w, acc0.x); acc0.y = fmaf(w.y, h0.w, acc0.y);
                acc0.z = fmaf(w.z, h0.w, acc0.z); acc0.w = fmaf(w.w, h0.w, acc0.w);
                acc1.x = fmaf(w.x, h1.w, acc1.x); acc1.y = fmaf(w.y, h1.w, acc1.y);
                acc1.z = fmaf(w.z, h1.w, acc1.z); acc1.w = fmaf(w.w, h1.w, acc1.w);
            }
        }

        // write partials: part[(g*2 + b)*256 + col]
        *(float4*)&part[(g * 2 + 0) * 256 + col] = acc0;
        *(float4*)&part[(g * 2 + 1) * 256 + col] = acc1;
        __syncthreads();

        // reduce 16 group-partials; threads < 512 own (rb, rk)
        if (reducer) {
            float s = 0.0f;
#pragma unroll
            for (int gg = 0; gg < 16; gg++) s += part[(gg * 2 + rb) * 256 + rk];
            hn = tanh_fast(xv + s);
            if (rb == 0) hs0[rk] = hn; else hs1[rk] = hn;
        }
        __syncthreads();
    }

    if (reducer) out[(size_t)(b0 + rb) * K_ + rk] = hn;
}

// =====================================================================
// Harness entry
// metadata order: inputs [B,T,D] f32, U [D,K] f32, W [K,K] f32, b [K] f32
// output: [B,1,K] f32
// =====================================================================
extern "C" void kernel_launch(void* const* d_in, const int* in_sizes, int n_in,
                              void* d_out, int out_size) {
    const float* X    = (const float*)d_in[0];
    const float* U    = (const float*)d_in[1];
    const float* W    = (const float*)d_in[2];
    const float* bias = (const float*)d_in[3];
    float* out = (float*)d_out;

    cudaError_t attr_rc = cudaFuncSetAttribute(
        rnn_recurrence_kernel,
        cudaFuncAttributeMaxDynamicSharedMemorySize,
        RNN_SMEM_BYTES);
    (void)attr_rc;

    u_split_kernel<<<D_ * K_ / 256, 256>>>(U);

    dim3 gemm_grid(B_ * T_ / 128, K_ / 128);   // (1024, 2)
    xu_gemm_mma_kernel<<<gemm_grid, 256>>>(X, bias);

    rnn_recurrence_kernel<<<128, 1024, RNN_SMEM_BYTES>>>(W, out);
}

// round 17
// speedup vs baseline: 1.6539x; 1.2362x over previous
#include <cuda_runtime.h>
#include <cuda_bf16.h>
#include <cstdint>
#include <math.h>

#define B_   256
#define T_   512
#define D_   256
#define K_   256

// Scratch: precomputed input projection xU [B, T, K] (134 MB).
__device__ float g_xu[(size_t)B_ * T_ * K_];
// U split into 2 bf16 planes (hi, mid): 16 mantissa bits total.
__device__ __nv_bfloat16 g_Uhi[D_ * K_];
__device__ __nv_bfloat16 g_Umid[D_ * K_];

// =====================================================================
// Kernel 0: split U into 2 bf16 planes.
// =====================================================================
__global__ void u_split_kernel(const float* __restrict__ U) {
    const int i = blockIdx.x * 256 + threadIdx.x;
    const float x = U[i];
    const __nv_bfloat16 hi = __float2bfloat16(x);
    const float r1 = x - __bfloat162float(hi);
    g_Uhi[i]  = hi;
    g_Umid[i] = __float2bfloat16(r1);
}

// =====================================================================
// Kernel 1: xU = X @ U + b via bf16 mma.sync, 2-plane split, 3 terms.
// (R11/R14 configuration, measured 175us == fallback-HMMA roofline.)
// =====================================================================
#define GBK 16
#define SA_STRIDE 24
#define SB_STRIDE 136

__device__ __forceinline__ unsigned smem_u32(const void* p) {
    return (unsigned)__cvta_generic_to_shared(p);
}
__device__ __forceinline__ void cp_async16(void* dst, const void* src) {
    asm volatile("cp.async.ca.shared.global [%0], [%1], 16;"
                 :: "r"(smem_u32(dst)), "l"(src));
}
__device__ __forceinline__ void cp_commit() {
    asm volatile("cp.async.commit_group;");
}
__device__ __forceinline__ void cp_wait_all() {
    asm volatile("cp.async.wait_group 0;");
}

__device__ __forceinline__ void ldm_x4(unsigned& r0, unsigned& r1, unsigned& r2, unsigned& r3, unsigned addr) {
    asm volatile("ldmatrix.sync.aligned.m8n8.x4.shared.b16 {%0,%1,%2,%3}, [%4];"
                 : "=r"(r0), "=r"(r1), "=r"(r2), "=r"(r3) : "r"(addr));
}
__device__ __forceinline__ void ldm_x2_trans(unsigned& r0, unsigned& r1, unsigned addr) {
    asm volatile("ldmatrix.sync.aligned.m8n8.x2.trans.shared.b16 {%0,%1}, [%2];"
                 : "=r"(r0), "=r"(r1) : "r"(addr));
}
__device__ __forceinline__ void mma_bf16(float* c, const unsigned* a, const unsigned* b) {
    asm volatile(
        "mma.sync.aligned.m16n8k16.row.col.f32.bf16.bf16.f32 "
        "{%0,%1,%2,%3}, {%4,%5,%6,%7}, {%8,%9}, {%0,%1,%2,%3};"
        : "+f"(c[0]), "+f"(c[1]), "+f"(c[2]), "+f"(c[3])
        : "r"(a[0]), "r"(a[1]), "r"(a[2]), "r"(a[3]), "r"(b[0]), "r"(b[1]));
}

__device__ __forceinline__ void split8(const float* xs, uint4& hq, uint4& mq) {
    unsigned h[4], m[4];
#pragma unroll
    for (int i = 0; i < 4; i++) {
        __nv_bfloat162 h2, m2;
        {
            const float x = xs[2 * i];
            const __nv_bfloat16 hi = __float2bfloat16(x);
            h2.x = hi; m2.x = __float2bfloat16(x - __bfloat162float(hi));
        }
        {
            const float x = xs[2 * i + 1];
            const __nv_bfloat16 hi = __float2bfloat16(x);
            h2.y = hi; m2.y = __float2bfloat16(x - __bfloat162float(hi));
        }
        h[i] = *(unsigned*)&h2;
        m[i] = *(unsigned*)&m2;
    }
    hq = make_uint4(h[0], h[1], h[2], h[3]);
    mq = make_uint4(m[0], m[1], m[2], m[3]);
}

__global__ __launch_bounds__(256) void xu_gemm_mma_kernel(
    const float* __restrict__ X,     // [B*T, D]
    const float* __restrict__ bias)  // [K]
{
    __shared__ __nv_bfloat16 sA[2][2][128][SA_STRIDE];
    __shared__ __nv_bfloat16 sB[2][2][GBK][SB_STRIDE];

    const int m0 = blockIdx.x * 128;
    const int n0 = blockIdx.y * 128;
    const int tid = (int)threadIdx.x;
    const int lane = tid & 31;
    const int wid = tid >> 5;
    const int wm = (wid >> 1) * 32;
    const int wn = (wid & 1) * 64;

    const int xa_row = tid >> 1;
    const int xa_cg  = (tid & 1) * 8;
    const int ub_k   = tid >> 4;
    const int ub_n   = (tid & 15) * 8;

    float c[2][8][4];
#pragma unroll
    for (int mt = 0; mt < 2; mt++)
#pragma unroll
        for (int nt = 0; nt < 8; nt++)
#pragma unroll
            for (int q = 0; q < 4; q++) c[mt][nt][q] = 0.0f;

    const int lq  = lane >> 3;
    const int lr  = lane & 7;
    const int a_r = (lq & 1) * 8 + lr;
    const int a_k = (lq >> 1) * 8;
    const int bl  = lane & 15;
    const int b_k = (bl >> 3) * 8 + (bl & 7);

    const float* xrow = &X[(size_t)(m0 + xa_row) * D_];

    {
        const float4 xv0 = *(const float4*)&xrow[xa_cg];
        const float4 xv1 = *(const float4*)&xrow[xa_cg + 4];
        float xs[8] = {xv0.x, xv0.y, xv0.z, xv0.w, xv1.x, xv1.y, xv1.z, xv1.w};
        uint4 hq, mq;
        split8(xs, hq, mq);
        *(uint4*)&sA[0][0][xa_row][xa_cg] = hq;
        *(uint4*)&sA[0][1][xa_row][xa_cg] = mq;

        const size_t uoff = (size_t)ub_k * K_ + (n0 + ub_n);
        cp_async16(&sB[0][0][ub_k][ub_n], &g_Uhi[uoff]);
        cp_async16(&sB[0][1][ub_k][ub_n], &g_Umid[uoff]);
        cp_commit();
    }
    cp_wait_all();
    __syncthreads();

    for (int iter = 0; iter < D_ / GBK; iter++) {
        const int cur = iter & 1;
        const int nxt = cur ^ 1;
        const bool more = (iter + 1) < (D_ / GBK);

        float xs[8];
        if (more) {
            const int k0n = (iter + 1) * GBK;
            const float4 xv0 = *(const float4*)&xrow[k0n + xa_cg];
            const float4 xv1 = *(const float4*)&xrow[k0n + xa_cg + 4];
            xs[0] = xv0.x; xs[1] = xv0.y; xs[2] = xv0.z; xs[3] = xv0.w;
            xs[4] = xv1.x; xs[5] = xv1.y; xs[6] = xv1.z; xs[7] = xv1.w;
            const size_t uoff = (size_t)(k0n + ub_k) * K_ + (n0 + ub_n);
            cp_async16(&sB[nxt][0][ub_k][ub_n], &g_Uhi[uoff]);
            cp_async16(&sB[nxt][1][ub_k][ub_n], &g_Umid[uoff]);
            cp_commit();
        }

        unsigned afr[2][2][4];
#pragma unroll
        for (int mt = 0; mt < 2; mt++) {
            const int row = wm + mt * 16 + a_r;
#pragma unroll
            for (int p = 0; p < 2; p++) {
                const unsigned addr = smem_u32(&sA[cur][p][row][a_k]);
                ldm_x4(afr[mt][p][0], afr[mt][p][1], afr[mt][p][2], afr[mt][p][3], addr);
            }
        }

#pragma unroll
        for (int nt = 0; nt < 8; nt++) {
            unsigned bfr[2][2];
#pragma unroll
            for (int p = 0; p < 2; p++) {
                const unsigned addr = smem_u32(&sB[cur][p][b_k][wn + nt * 8]);
                ldm_x2_trans(bfr[p][0], bfr[p][1], addr);
            }
#pragma unroll
            for (int mt = 0; mt < 2; mt++) {
                mma_bf16(c[mt][nt], afr[mt][0], bfr[0]);   // hi*hi
                mma_bf16(c[mt][nt], afr[mt][0], bfr[1]);   // hi*mid
                mma_bf16(c[mt][nt], afr[mt][1], bfr[0]);   // mid*hi
            }
        }

        if (more) {
            uint4 hq, mq;
            split8(xs, hq, mq);
            *(uint4*)&sA[nxt][0][xa_row][xa_cg] = hq;
            *(uint4*)&sA[nxt][1][xa_row][xa_cg] = mq;
            cp_wait_all();
        }
        __syncthreads();
    }

    const int gid = lane >> 2;
    const int tig = lane & 3;
#pragma unroll
    for (int nt = 0; nt < 8; nt++) {
        const int col = n0 + wn + nt * 8 + 2 * tig;
        const float2 bv = *(const float2*)&bias[col];
#pragma unroll
        for (int mt = 0; mt < 2; mt++) {
            const size_t r0 = (size_t)(m0 + wm + mt * 16 + gid);
            float2 v0; v0.x = c[mt][nt][0] + bv.x; v0.y = c[mt][nt][1] + bv.y;
            float2 v1; v1.x = c[mt][nt][2] + bv.x; v1.y = c[mt][nt][3] + bv.y;
            *(float2*)&g_xu[r0 * K_ + col]       = v0;
            *(float2*)&g_xu[(r0 + 8) * K_ + col] = v1;
        }
    }
}

// =====================================================================
// Kernel 2: persistent per-batch recurrence, 512 threads/block.
// W rows 0..95 in smem (96 KB, -25% smem W traffic vs R14), rows
// 96..255 in registers (20 float4/thread, ~110 regs total).
// Group g (tid>>6): smem rows [12g,12g+12), reg rows [96+20g,96+20g+20).
// Threads own 4 cols each; partials (8 groups x 2 batches) -> smem
// reduce by 512 threads, tanh.approx, 2 barriers/step.
// =====================================================================
#define W_SMEM_ROWS 96
#define W_REG_ROWS  20
#define RNN_SMEM_FLOATS (W_SMEM_ROWS * 256 + 2 * 256 + 16 * 256)
#define RNN_SMEM_BYTES  (RNN_SMEM_FLOATS * 4)

__device__ __forceinline__ float tanh_fast(float x) {
    float y;
    asm("tanh.approx.f32 %0, %1;" : "=f"(y) : "f"(x));
    return y;
}

__global__ __launch_bounds__(512, 1) void rnn_recurrence_kernel(
    const float* __restrict__ W,    // [K, K] row-major: W[j*K + k]
    float* __restrict__ out)        // [B, K]
{
    extern __shared__ float sm[];
    float* Wsm  = sm;                          // 96*256 floats
    float* hs0  = sm + W_SMEM_ROWS * 256;      // 256 floats: h batch b0
    float* hs1  = hs0 + 256;                   // 256 floats: h batch b1
    float* part = hs1 + 256;                   // 16*256 floats

    const int tid = (int)threadIdx.x;
    const int g   = tid >> 6;        // 0..7
    const int c   = tid & 63;        // 0..63
    const int col = c * 4;           // base column (k)
    const int b0  = blockIdx.x * 2;

    // --- W rows 0..95 into smem (512 threads x 12 float4) ---
    for (int i = tid; i < W_SMEM_ROWS * 64; i += 512) {
        const int row = i >> 6;
        const int c4  = (i & 63) * 4;
        *(float4*)&Wsm[row * 256 + c4] = *(const float4*)&W[row * 256 + c4];
    }
    // --- W rows [96+20g, 96+20g+20) into registers for this thread's cols ---
    float4 wreg[W_REG_ROWS];
#pragma unroll
    for (int jj = 0; jj < W_REG_ROWS; jj++) {
        wreg[jj] = *(const float4*)&W[(W_SMEM_ROWS + g * W_REG_ROWS + jj) * 256 + col];
    }
    if (tid < 256) { hs0[tid] = 0.0f; hs1[tid] = 0.0f; }
    __syncthreads();

    // Reduce ownership: thread -> (batch rb, column rk)
    const int rb = tid >> 8;         // 0 or 1
    const int rk = tid & 255;        // 0..255
    const float* xup = g_xu + ((size_t)(b0 + rb) * T_) * K_ + rk;

    const int js = g * 12;                        // smem j base
    const int jr = W_SMEM_ROWS + g * W_REG_ROWS;  // reg j base
    float hn = 0.0f;

    for (int ts = 0; ts < T_; ts++) {
        const float xv = xup[(size_t)ts * K_];   // issued early, used after BAR1

        float4 acc0 = make_float4(0.f, 0.f, 0.f, 0.f);
        float4 acc1 = make_float4(0.f, 0.f, 0.f, 0.f);

        // smem W rows [12g, 12g+12), h loaded as float4 (4 j's per load)
#pragma unroll
        for (int jj = 0; jj < 12; jj += 4) {
            const float4 h0 = *(const float4*)&hs0[js + jj];
            const float4 h1 = *(const float4*)&hs1[js + jj];
            {
                const float4 w = *(const float4*)&Wsm[(js + jj + 0) * 256 + col];
                acc0.x = fmaf(w.x, h0.x, acc0.x); acc0.y = fmaf(w.y, h0.x, acc0.y);
                acc0.z = fmaf(w.z, h0.x, acc0.z); acc0.w = fmaf(w.w, h0.x, acc0.w);
                acc1.x = fmaf(w.x, h1.x, acc1.x); acc1.y = fmaf(w.y, h1.x, acc1.y);
                acc1.z = fmaf(w.z, h1.x, acc1.z); acc1.w = fmaf(w.w, h1.x, acc1.w);
            }
            {
                const float4 w = *(const float4*)&Wsm[(js + jj + 1) * 256 + col];
                acc0.x = fmaf(w.x, h0.y, acc0.x); acc0.y = fmaf(w.y, h0.y, acc0.y);
                acc0.z = fmaf(w.z, h0.y, acc0.z); acc0.w = fmaf(w.w, h0.y, acc0.w);
                acc1.x = fmaf(w.x, h1.y, acc1.x); acc1.y = fmaf(w.y, h1.y, acc1.y);
                acc1.z = fmaf(w.z, h1.y, acc1.z); acc1.w = fmaf(w.w, h1.y, acc1.w);
            }
            {
                const float4 w = *(const float4*)&Wsm[(js + jj + 2) * 256 + col];
                acc0.x = fmaf(w.x, h0.z, acc0.x); acc0.y = fmaf(w.y, h0.z, acc0.y);
                acc0.z = fmaf(w.z, h0.z, acc0.z); acc0.w = fmaf(w.w, h0.z, acc0.w);
                acc1.x = fmaf(w.x, h1.z, acc1.x); acc1.y = fmaf(w.y, h1.z, acc1.y);
                acc1.z = fmaf(w.z, h1.z, acc1.z); acc1.w = fmaf(w.w, h1.z, acc1.w);
            }
            {
                const float4 w = *(const float4*)&Wsm[(js + jj + 3) * 256 + col];
                acc0.x = fmaf(w.x, h0.w, acc0.x); acc0.y = fmaf(w.y, h0.w, acc0.y);
                acc0.z = fmaf(w.z, h0.w, acc0.z); acc0.w = fmaf(w.w, h0.w, acc0.w);
                acc1.x = fmaf(w.x, h1.w, acc1.x); acc1.y = fmaf(w.y, h1.w, acc1.y);
                acc1.z = fmaf(w.z, h1.w, acc1.z); acc1.w = fmaf(w.w, h1.w, acc1.w);
            }
        }
        // register W rows [96+20g, 96+20g+20)
#pragma unroll
        for (int jj = 0; jj < W_REG_ROWS; jj += 4) {
            const float4 h0 = *(const float4*)&hs0[jr + jj];
            const float4 h1 = *(const float4*)&hs1[jr + jj];
            {
                const float4 w = wreg[jj + 0];
                acc0.x = fmaf(w.x, h0.x, acc0.x); acc0.y = fmaf(w.y, h0.x, acc0.y);
                acc0.z = fmaf(w.z, h0.x, acc0.z); acc0.w = fmaf(w.w, h0.x, acc0.w);
                acc1.x = fmaf(w.x, h1.x, acc1.x); acc1.y = fmaf(w.y, h1.x, acc1.y);
                acc1.z = fmaf(w.z, h1.x, acc1.z); acc1.w = fmaf(w.w, h1.x, acc1.w);
            }
            {
                const float4 w = wreg[jj + 1];
                acc0.x = fmaf(w.x, h0.y, acc0.x); acc0.y = fmaf(w.y, h0.y, acc0.y);
                acc0.z = fmaf(w.z, h0.y, acc0.z); acc0.w = fmaf(w.w, h0.y, acc0.w);
                acc1.x = fmaf(w.x, h1.y, acc1.x); acc1.y = fmaf(w.y, h1.y, acc1.y);
                acc1.z = fmaf(w.z, h1.y, acc1.z); acc1.w = fmaf(w.w, h1.y, acc1.w);
            }
            {
                const float4 w = wreg[jj + 2];
                acc0.x = fmaf(w.x, h0.z, acc0.x); acc0.y = fmaf(w.y, h0.z, acc0.y);
                acc0.z = fmaf(w.z, h0.z, acc0.z); acc0.w = fmaf(w.w, h0.z, acc0.w);
                acc1.x = fmaf(w.x, h1.z, acc1.x); acc1.y = fmaf(w.y, h1.z, acc1.y);
                acc1.z = fmaf(w.z, h1.z, acc1.z); acc1.w = fmaf(w.w, h1.z, acc1.w);
            }
            {
                const float4 w = wreg[jj + 3];
                acc0.x = fmaf(w.x, h0.w, acc0.x); acc0.y = fmaf(w.y, h0.w, acc0.y);
                acc0.z = fmaf(w.z, h0.w, acc0.z); acc0.w = fmaf(w.w, h0.w, acc0.w);
                acc1.x = fmaf(w.x, h1.w, acc1.x); acc1.y = fmaf(w.y, h1.w, acc1.y);
                acc1.z = fmaf(w.z, h1.w, acc1.z); acc1.w = fmaf(w.w, h1.w, acc1.w);
            }
        }

        // write partials: part[(g*2 + b)*256 + col]
        *(float4*)&part[(g * 2 + 0) * 256 + col] = acc0;
        *(float4*)&part[(g * 2 + 1) * 256 + col] = acc1;
        __syncthreads();

        // reduce the 8 group-partials; thread owns (rb, rk)
        float s = 0.0f;
#pragma unroll
        for (int gg = 0; gg < 8; gg++) s += part[(gg * 2 + rb) * 256 + rk];

        hn = tanh_fast(xv + s);
        if (rb == 0) hs0[rk] = hn; else hs1[rk] = hn;
        __syncthreads();
    }

    out[(size_t)(b0 + rb) * K_ + rk] = hn;
}

// =====================================================================
// Harness entry
// metadata order: inputs [B,T,D] f32, U [D,K] f32, W [K,K] f32, b [K] f32
// output: [B,1,K] f32
// =====================================================================
extern "C" void kernel_launch(void* const* d_in, const int* in_sizes, int n_in,
                              void* d_out, int out_size) {
    const float* X    = (const float*)d_in[0];
    const float* U    = (const float*)d_in[1];
    const float* W    = (const float*)d_in[2];
    const float* bias = (const float*)d_in[3];
    float* out = (float*)d_out;

    cudaError_t attr_rc = cudaFuncSetAttribute(
        rnn_recurrence_kernel,
        cudaFuncAttributeMaxDynamicSharedMemorySize,
        RNN_SMEM_BYTES);
    (void)attr_rc;

    u_split_kernel<<<D_ * K_ / 256, 256>>>(U);

    dim3 gemm_grid(B_ * T_ / 128, K_ / 128);   // (1024, 2)
    xu_gemm_mma_kernel<<<gemm_grid, 256>>>(X, bias);

    rnn_recurrence_kernel<<<128, 512, RNN_SMEM_BYTES>>>(W, out);
}